// round 10
// baseline (speedup 1.0000x reference)
#include <cuda_runtime.h>
#include <cuda_fp16.h>
#include <cstdint>
#include <math.h>

// Problem constants
#define NB   16
#define NC   512
#define NL   4096
#define ND   384
#define NTOK 256
#define NROWS 4096      // NB*NTOK
#define NINNER 512
#define NFF  1536
#define NHEADS 8
#define NDH  64

// ---------------------------------------------------------------------------
// Scratch (device globals; allocation-free)
// ---------------------------------------------------------------------------
__device__ alignas(16) float  g_h  [NROWS*ND];      // residual stream (fp32)
__device__ alignas(16) float  g_t3 [NROWS*ND];      // conv out (fp32)
__device__ alignas(16) float  g_hp [NROWS*NC];      // hp for final (fp32)
__device__ alignas(16) __half g_xp [NROWS*NINNER];  // pool out / attn out (half)
__device__ alignas(16) __half g_t2h[NROWS*ND];      // LN outputs (half)
__device__ alignas(16) __half g_yh [NROWS*NFF];     // qkv / ff1 (half)
// half weights
__device__ alignas(16) __half g_wqkvH[2*ND*NFF];    // [K=384][N=1536]
__device__ alignas(16) __half g_ffw1H[2*ND*NFF];    // [K=384][N=1536]
__device__ alignas(16) __half g_ffw2H[2*NFF*ND];    // [K=1536][N=384]
__device__ alignas(16) __half g_woutH[2*NINNER*ND]; // [K=512][N=384]
__device__ alignas(16) __half g_wAH[NC*ND];         // proj_in^T  [512][384]
__device__ alignas(16) __half g_wBH[ND*NC];         // proj_out^T [384][512]
__device__ alignas(16) __half g_wtH[3*ND*ND];       // conv [K=1152][N=384]

__device__ __forceinline__ float gelu_exact(float v) { return v * normcdff(v); }

__device__ __forceinline__ float4 ld4h(const __half* p) {
    uint2 u = *(const uint2*)p;
    float2 fa = __half22float2(*(__half2*)&u.x);
    float2 fb = __half22float2(*(__half2*)&u.y);
    return make_float4(fa.x, fa.y, fb.x, fb.y);
}
__device__ __forceinline__ void st4h(__half* p, float4 v) {
    uint2 u;
    *(__half2*)&u.x = __floats2half2_rn(v.x, v.y);
    *(__half2*)&u.y = __floats2half2_rn(v.z, v.w);
    *(uint2*)p = u;
}

__device__ __forceinline__ void mma_f16(float (&d)[4], const unsigned (&a)[4],
                                        const unsigned (&b)[2]) {
    asm volatile(
        "mma.sync.aligned.m16n8k16.row.col.f32.f16.f16.f32 "
        "{%0,%1,%2,%3}, {%4,%5,%6,%7}, {%8,%9}, {%0,%1,%2,%3};\n"
        : "+f"(d[0]), "+f"(d[1]), "+f"(d[2]), "+f"(d[3])
        : "r"(a[0]), "r"(a[1]), "r"(a[2]), "r"(a[3]), "r"(b[0]), "r"(b[1]));
}

__device__ __forceinline__ void ldsm4(unsigned (&r)[4], uint32_t addr) {
    asm volatile("ldmatrix.sync.aligned.m8n8.x4.shared.b16 {%0,%1,%2,%3}, [%4];"
                 : "=r"(r[0]), "=r"(r[1]), "=r"(r[2]), "=r"(r[3]) : "r"(addr));
}
__device__ __forceinline__ void ldsm4t(unsigned& r0, unsigned& r1,
                                       unsigned& r2, unsigned& r3, uint32_t addr) {
    asm volatile("ldmatrix.sync.aligned.m8n8.x4.trans.shared.b16 {%0,%1,%2,%3}, [%4];"
                 : "=r"(r0), "=r"(r1), "=r"(r2), "=r"(r3) : "r"(addr));
}

// ---------------------------------------------------------------------------
// fp16 mma.sync GEMM. BM=64, BN=128, BK=32. 256 threads = 8 warps (4x2);
// warp tile 16x64. Register-staged double buffer, ONE sync per K-slice.
// LDA=40 halves (80B rows), LDB=136 (272B): 16B-aligned, conflict-free.
// CONV=1: A is gathered on-the-fly from fp32 h with +-1 token shift.
// OUTH=1: half output. ACC adds fp32 Cin. ACT=1: exact GELU.
// ---------------------------------------------------------------------------
template<int ACT, bool ACC, int OUTH, int CONV>
__global__ __launch_bounds__(256, 2) void hgemm(
    const void* __restrict__ Av, const __half* __restrict__ Bw,
    const float* __restrict__ bias, const float* __restrict__ Cin,
    void* __restrict__ Cv, int M, int N, int K)
{
    constexpr int LDA = 40;
    constexpr int LDB = 136;

    __shared__ alignas(16) __half As[2][64 * LDA];
    __shared__ alignas(16) __half Bs[2][32 * LDB];

    const int tid = threadIdx.x;
    const int warp = tid >> 5, lane = tid & 31;
    const int wr = warp >> 1, wc = warp & 1;      // 4 x 2 warps
    const int wm = wr * 16, wn = wc * 64;
    const int m0 = blockIdx.y * 64, n0 = blockIdx.x * 128;
    const int NS = K >> 5;

    const __half* A  = (const __half*)Av;
    const float*  Hc = (const float*)Av;

    float acc[8][4];
#pragma unroll
    for (int nt = 0; nt < 8; nt++)
#pragma unroll
        for (int i = 0; i < 4; i++) acc[nt][i] = 0.f;

    uint4 stA, stB[2];
    const int a_row = tid >> 2, a_ch = tid & 3;

    auto loadA = [&](int s) {
        if (CONV) {
            int k0 = s * 32 + a_ch * 8;
            int seg = k0 / ND;
            int col = k0 - seg * ND;
            int gr = m0 + a_row;
            int n = gr & 255;
            bool ok = (seg == 1) || (seg == 0 && n > 0) || (seg == 2 && n < 255);
            float4 f0 = make_float4(0.f, 0.f, 0.f, 0.f), f1 = f0;
            if (ok) {
                const float* p = Hc + (size_t)(gr + seg - 1) * ND + col;
                f0 = *(const float4*)p;
                f1 = *(const float4*)(p + 4);
            }
            uint4 u;
            *(__half2*)&u.x = __floats2half2_rn(f0.x, f0.y);
            *(__half2*)&u.y = __floats2half2_rn(f0.z, f0.w);
            *(__half2*)&u.z = __floats2half2_rn(f1.x, f1.y);
            *(__half2*)&u.w = __floats2half2_rn(f1.z, f1.w);
            stA = u;
        } else {
            stA = *(const uint4*)(A + (size_t)(m0 + a_row) * K + s * 32 + a_ch * 8);
        }
    };
    auto loadB = [&](int s) {
#pragma unroll
        for (int i = 0; i < 2; i++) {
            int lin = tid + i * 256;
            int row = lin >> 4, c8 = (lin & 15) << 3;
            stB[i] = *(const uint4*)(Bw + (size_t)(s * 32 + row) * N + n0 + c8);
        }
    };

    loadA(0); loadB(0);

    for (int s = 0; s < NS; s++) {
        const int buf = s & 1;
        *(uint4*)&As[buf][a_row * LDA + a_ch * 8] = stA;
#pragma unroll
        for (int i = 0; i < 2; i++) {
            int lin = tid + i * 256;
            int row = lin >> 4, c8 = (lin & 15) << 3;
            *(uint4*)&Bs[buf][row * LDB + c8] = stB[i];
        }
        // issue next-slice global loads before the barrier (overlap)
        if (s + 1 < NS) { loadA(s + 1); loadB(s + 1); }
        __syncthreads();

#pragma unroll
        for (int ks = 0; ks < 2; ks++) {
            unsigned af[4], bf[8][2];
            uint32_t aa = (uint32_t)__cvta_generic_to_shared(
                &As[buf][(wm + (lane & 15)) * LDA + ks * 16 + ((lane >> 4) << 3)]);
            ldsm4(af, aa);
#pragma unroll
            for (int np = 0; np < 4; np++) {
                uint32_t ba = (uint32_t)__cvta_generic_to_shared(
                    &Bs[buf][(ks * 16 + (lane & 15)) * LDB + wn + np * 16 + ((lane >> 4) << 3)]);
                ldsm4t(bf[np * 2][0], bf[np * 2][1], bf[np * 2 + 1][0], bf[np * 2 + 1][1], ba);
            }
#pragma unroll
            for (int nt = 0; nt < 8; nt++)
                mma_f16(acc[nt], af, bf[nt]);
        }
    }

    // epilogue
#pragma unroll
    for (int nt = 0; nt < 8; nt++) {
#pragma unroll
        for (int half_i = 0; half_i < 2; half_i++) {
            const int row = m0 + wm + (lane >> 2) + half_i * 8;
            const int col = n0 + wn + nt * 8 + (lane & 3) * 2;
            float2 r;
            r.x = acc[nt][half_i * 2];
            r.y = acc[nt][half_i * 2 + 1];
            if (bias) { r.x += bias[col]; r.y += bias[col + 1]; }
            if (ACT == 1) { r.x = gelu_exact(r.x); r.y = gelu_exact(r.y); }
            if (ACC) {
                const float* cp = Cin + (size_t)row * N + col;
                r.x += cp[0]; r.y += cp[1];
            }
            if (OUTH) {
                __half2* cp = (__half2*)((__half*)Cv + (size_t)row * N + col);
                *cp = __floats2half2_rn(r.x, r.y);
            } else {
                *(float2*)((float*)Cv + (size_t)row * N + col) = r;
            }
        }
    }
}

// ---------------------------------------------------------------------------
// Fused weight prep: converts/transposes ALL weights in one launch.
//  blocks [0, 3840): fp32->half copies (wqkv, ffw1, ffw2, wout)
//  blocks [3840, 4032): transpose proj_in_w -> wAH
//  blocks [4032, 4224): transpose proj_out_w -> wBH
//  blocks [4224, 5952): conv weight reshape -> wtH
// ---------------------------------------------------------------------------
#define WP_N1 (2*ND*NFF/4)      // 294912
#define WP_N4 (2*NINNER*ND/4)   // 98304
#define PRE1 3840
#define PRE2 (PRE1 + 192)
#define PRE3 (PRE2 + 192)
#define PRE4 (PRE3 + 1728)
__global__ __launch_bounds__(256) void prep_all(
    const float* __restrict__ wqkv, const float* __restrict__ ffw1,
    const float* __restrict__ ffw2, const float* __restrict__ wout,
    const float* __restrict__ proj_in_w, const float* __restrict__ proj_out_w,
    const float* __restrict__ local_w,
    __half* __restrict__ o1, __half* __restrict__ o2,
    __half* __restrict__ o3, __half* __restrict__ o4,
    __half* __restrict__ wAH, __half* __restrict__ wBH, __half* __restrict__ wtH)
{
    __shared__ float tt[32][33];
    const int blk = blockIdx.x, t = threadIdx.x;
    if (blk < PRE1) {
        int i = blk * 256 + t;
        const float* src; __half* dst; int j;
        if (i < WP_N1)          { src = wqkv; dst = o1; j = i; }
        else if (i < 2 * WP_N1) { src = ffw1; dst = o2; j = i - WP_N1; }
        else if (i < 3 * WP_N1) { src = ffw2; dst = o3; j = i - 2 * WP_N1; }
        else                    { src = wout; dst = o4; j = i - 3 * WP_N1; }
        st4h(dst + (size_t)j * 4, ((const float4*)src)[j]);
    } else if (blk < PRE3) {
        int R, Cc, bx, by;
        const float* src; __half* dst;
        if (blk < PRE2) { int b = blk - PRE1; R = ND; Cc = NC; bx = b % 16; by = b / 16; src = proj_in_w;  dst = wAH; }
        else            { int b = blk - PRE2; R = NC; Cc = ND; bx = b % 12; by = b / 12; src = proj_out_w; dst = wBH; }
        int tx = t & 31, ty = t >> 5;
        int c = bx * 32 + tx, r = by * 32 + ty;
#pragma unroll
        for (int i = 0; i < 32; i += 8)
            tt[ty + i][tx] = src[(size_t)(r + i) * Cc + c];
        __syncthreads();
        int co = by * 32 + tx, ro = bx * 32 + ty;
#pragma unroll
        for (int i = 0; i < 32; i += 8)
            dst[(size_t)(ro + i) * R + co] = __float2half(tt[tx][ty + i]);
    } else {
        int idx = (blk - PRE3) * 256 + t;
        int krow = idx / ND, dout = idx - krow * ND;
        int k = krow / ND, din = krow - k * ND;
        wtH[idx] = __float2half(local_w[(dout * ND + din) * 3 + k]);
    }
}

// ---------------------------------------------------------------------------
// Pool: x[B,C,L] -> xpT[(b*256+n), c] (half), mean over windows of 16
// ---------------------------------------------------------------------------
__global__ __launch_bounds__(256) void pool_kernel(const float* __restrict__ x,
                                                   __half* __restrict__ xpT)
{
    int bc = blockIdx.x;
    int b = bc >> 9, c = bc & 511;
    const float4* src = (const float4*)(x + (size_t)bc * NL) + threadIdx.x * 4;
    float s = 0.f;
#pragma unroll
    for (int j = 0; j < 4; j++) {
        float4 v = src[j];
        s += v.x + v.y + v.z + v.w;
    }
    xpT[((size_t)(b * NTOK + threadIdx.x)) * NC + c] = __float2half(s * (1.f / 16.f));
}

// ---------------------------------------------------------------------------
// LayerNorm over last dim (384). Warp per row. OUTH: half output.
// ---------------------------------------------------------------------------
template<int OUTH>
__global__ __launch_bounds__(256) void ln_kernel(const float* __restrict__ in,
                                                 const float* __restrict__ g,
                                                 const float* __restrict__ b,
                                                 void* __restrict__ outv)
{
    const int wid = threadIdx.x >> 5, lane = threadIdx.x & 31;
    const int row = blockIdx.x * 8 + wid;
    const float* xr = in + (size_t)row * ND;
    float4 v0 = *(const float4*)(xr + lane * 4);
    float4 v1 = *(const float4*)(xr + 128 + lane * 4);
    float4 v2 = *(const float4*)(xr + 256 + lane * 4);
    float s = v0.x + v0.y + v0.z + v0.w + v1.x + v1.y + v1.z + v1.w
            + v2.x + v2.y + v2.z + v2.w;
    float q = v0.x*v0.x + v0.y*v0.y + v0.z*v0.z + v0.w*v0.w
            + v1.x*v1.x + v1.y*v1.y + v1.z*v1.z + v1.w*v1.w
            + v2.x*v2.x + v2.y*v2.y + v2.z*v2.z + v2.w*v2.w;
#pragma unroll
    for (int o = 16; o; o >>= 1) {
        s += __shfl_xor_sync(0xFFFFFFFFu, s, o);
        q += __shfl_xor_sync(0xFFFFFFFFu, q, o);
    }
    const float mean = s * (1.f / ND);
    const float var  = q * (1.f / ND) - mean * mean;
    const float inv  = rsqrtf(var + 1e-5f);
#pragma unroll
    for (int j = 0; j < 3; j++) {
        int col = j * 128 + lane * 4;
        float4 v = (j == 0) ? v0 : (j == 1) ? v1 : v2;
        float4 gg = *(const float4*)(g + col);
        float4 bb = *(const float4*)(b + col);
        float4 r;
        r.x = (v.x - mean) * inv * gg.x + bb.x;
        r.y = (v.y - mean) * inv * gg.y + bb.y;
        r.z = (v.z - mean) * inv * gg.z + bb.z;
        r.w = (v.w - mean) * inv * gg.w + bb.w;
        if (OUTH) st4h((__half*)outv + (size_t)row * ND + col, r);
        else      *(float4*)((float*)outv + (size_t)row * ND + col) = r;
    }
}

// ---------------------------------------------------------------------------
// Linear attention per (b,h); half in (qkv), half out. Internal fp32.
// ---------------------------------------------------------------------------
__device__ __forceinline__ void r1u(float (&acc)[4][4], float a0, float a1,
                                    float a2, float a3, const float4 b)
{
    acc[0][0] += a0 * b.x; acc[0][1] += a0 * b.y; acc[0][2] += a0 * b.z; acc[0][3] += a0 * b.w;
    acc[1][0] += a1 * b.x; acc[1][1] += a1 * b.y; acc[1][2] += a1 * b.z; acc[1][3] += a1 * b.w;
    acc[2][0] += a2 * b.x; acc[2][1] += a2 * b.y; acc[2][2] += a2 * b.z; acc[2][3] += a2 * b.w;
    acc[3][0] += a3 * b.x; acc[3][1] += a3 * b.y; acc[3][2] += a3 * b.z; acc[3][3] += a3 * b.w;
}

__global__ __launch_bounds__(256) void attn_kernel(const __half* __restrict__ qkv,
                                                   const float* __restrict__ rf,
                                                   __half* __restrict__ o)
{
    __shared__ float rf_s[4096];
    __shared__ float bufA[4096];
    __shared__ float bufB[4096];
    const int tid = threadIdx.x;
    const int bh = blockIdx.x;
    const int b = bh >> 3, h = bh & 7;
    const int tq = tid >> 4, tr = tid & 15;

#pragma unroll
    for (int j = 0; j < 4; j++)
        ((float4*)rf_s)[tid + j * 256] = ((const float4*)rf)[tid + j * 256];

    const __half* base = qkv + (size_t)b * NTOK * NFF + h * NDH;

    float kv[4][4];
#pragma unroll
    for (int i = 0; i < 4; i++)
#pragma unroll
        for (int j = 0; j < 4; j++) kv[i][j] = 0.f;

    for (int n0 = 0; n0 < NTOK; n0 += 64) {
        __syncthreads();
#pragma unroll
        for (int j = 0; j < 4; j++) {
            int lin = tid + j * 256;
            int rowi = lin >> 4, c4 = (lin & 15) << 2;
            const __half* rp = base + (size_t)(n0 + rowi) * NFF;
            float4 kk = ld4h(rp + NINNER + c4);
            kk.x = fmaxf(kk.x, 0.f); kk.y = fmaxf(kk.y, 0.f);
            kk.z = fmaxf(kk.z, 0.f); kk.w = fmaxf(kk.w, 0.f);
            *(float4*)&bufA[rowi * 64 + c4] = kk;
            *(float4*)&bufB[rowi * 64 + c4] = ld4h(rp + 2 * NINNER + c4);
        }
        __syncthreads();
#pragma unroll 8
        for (int nn = 0; nn < 64; nn++) {
            float4 ka = *(const float4*)&bufA[nn * 64 + tq * 4];
            float4 vb = *(const float4*)&bufB[nn * 64 + tr * 4];
            r1u(kv, ka.x, ka.y, ka.z, ka.w, vb);
        }
    }
    __syncthreads();
#pragma unroll
    for (int i = 0; i < 4; i++) {
        float4 v = make_float4(kv[i][0], kv[i][1], kv[i][2], kv[i][3]);
        *(float4*)&bufA[(tq * 4 + i) * 64 + tr * 4] = v;
    }
    __syncthreads();

    float w1[4][4];
#pragma unroll
    for (int i = 0; i < 4; i++)
#pragma unroll
        for (int j = 0; j < 4; j++) w1[i][j] = 0.f;
#pragma unroll 8
    for (int dk = 0; dk < 64; dk++) {
        float4 rm = *(const float4*)&rf_s[dk * 64 + tq * 4];
        float4 kd = *(const float4*)&bufA[dk * 64 + tr * 4];
        r1u(w1, rm.x, rm.y, rm.z, rm.w, kd);
    }
    __syncthreads();
#pragma unroll
    for (int i = 0; i < 4; i++) {
        float4 v = make_float4(w1[i][0], w1[i][1], w1[i][2], w1[i][3]);
        *(float4*)&bufB[(tq * 4 + i) * 64 + tr * 4] = v;
    }
    __syncthreads();

    float w2[4][4];
#pragma unroll
    for (int i = 0; i < 4; i++)
#pragma unroll
        for (int j = 0; j < 4; j++) w2[i][j] = 0.f;
#pragma unroll 8
    for (int m = 0; m < 64; m++) {
        float4 wd = *(const float4*)&bufB[m * 64 + tr * 4];
        float r0 = rf_s[(tq * 4 + 0) * 64 + m];
        float r1 = rf_s[(tq * 4 + 1) * 64 + m];
        float r2 = rf_s[(tq * 4 + 2) * 64 + m];
        float r3 = rf_s[(tq * 4 + 3) * 64 + m];
        r1u(w2, r0, r1, r2, r3, wd);
    }
    __syncthreads();
#pragma unroll
    for (int i = 0; i < 4; i++) {
        float4 v = make_float4(w2[i][0], w2[i][1], w2[i][2], w2[i][3]);
        *(float4*)&bufA[(tq * 4 + i) * 64 + tr * 4] = v;
    }
    __syncthreads();

    for (int n0 = 0; n0 < NTOK; n0 += 64) {
#pragma unroll
        for (int j = 0; j < 4; j++) {
            int lin = tid + j * 256;
            int rowi = lin >> 4, c4 = (lin & 15) << 2;
            const __half* rp = base + (size_t)(n0 + rowi) * NFF;
            float4 qq = ld4h(rp + c4);
            qq.x = fmaxf(qq.x, 0.f) * 0.125f; qq.y = fmaxf(qq.y, 0.f) * 0.125f;
            qq.z = fmaxf(qq.z, 0.f) * 0.125f; qq.w = fmaxf(qq.w, 0.f) * 0.125f;
            *(float4*)&bufB[rowi * 64 + c4] = qq;
        }
        __syncthreads();
        float oc[4][4];
#pragma unroll
        for (int i = 0; i < 4; i++)
#pragma unroll
            for (int j = 0; j < 4; j++) oc[i][j] = 0.f;
#pragma unroll 8
        for (int dq = 0; dq < 64; dq++) {
            float4 wd = *(const float4*)&bufA[dq * 64 + tr * 4];
            float q0 = bufB[(tq * 4 + 0) * 64 + dq];
            float q1 = bufB[(tq * 4 + 1) * 64 + dq];
            float q2 = bufB[(tq * 4 + 2) * 64 + dq];
            float q3 = bufB[(tq * 4 + 3) * 64 + dq];
            r1u(oc, q0, q1, q2, q3, wd);
        }
#pragma unroll
        for (int i = 0; i < 4; i++) {
            st4h(o + (size_t)(b * NTOK + n0 + tq * 4 + i) * NINNER + h * NDH + tr * 4,
                 make_float4(oc[i][0], oc[i][1], oc[i][2], oc[i][3]));
        }
        __syncthreads();
    }
}

// ---------------------------------------------------------------------------
// Final: out[b,c,l] = interp(hp)[b,c,l] + x[b,c,l]
// ---------------------------------------------------------------------------
__global__ __launch_bounds__(256) void final_kernel(const float* __restrict__ hp,
                                                    const float* __restrict__ x,
                                                    float* __restrict__ out)
{
    size_t idx = (size_t)blockIdx.x * 256 + threadIdx.x;
    int l = (int)(idx & 4095);
    int c = (int)((idx >> 12) & 511);
    int b = (int)(idx >> 21);
    float src = fmaxf((l + 0.5f) * 0.0625f - 0.5f, 0.f);
    int i0 = (int)src;
    float w = src - (float)i0;
    int i1 = min(i0 + 1, 255);
    float v0 = hp[(size_t)(b * NTOK + i0) * NC + c];
    float v1 = hp[(size_t)(b * NTOK + i1) * NC + c];
    out[idx] = v0 * (1.f - w) + v1 * w + x[idx];
}

// ---------------------------------------------------------------------------
// Host orchestration
// ---------------------------------------------------------------------------
extern "C" void kernel_launch(void* const* d_in, const int* in_sizes, int n_in,
                              void* d_out, int out_size)
{
    const float* x          = (const float*)d_in[0];
    const float* proj_in_w  = (const float*)d_in[1];
    const float* proj_in_b  = (const float*)d_in[2];
    const float* norm_in_g  = (const float*)d_in[3];
    const float* norm_in_b  = (const float*)d_in[4];
    const float* ln1_g      = (const float*)d_in[5];
    const float* ln1_b      = (const float*)d_in[6];
    const float* wqkv       = (const float*)d_in[7];
    const float* rf         = (const float*)d_in[8];
    const float* wout       = (const float*)d_in[9];
    const float* bout       = (const float*)d_in[10];
    const float* ln2_g      = (const float*)d_in[11];
    const float* ln2_b      = (const float*)d_in[12];
    const float* ffw1       = (const float*)d_in[13];
    const float* ffb1       = (const float*)d_in[14];
    const float* ffw2       = (const float*)d_in[15];
    const float* ffb2       = (const float*)d_in[16];
    const float* local_w    = (const float*)d_in[17];
    const float* local_b    = (const float*)d_in[18];
    const float* norm_out_g = (const float*)d_in[19];
    const float* norm_out_b = (const float*)d_in[20];
    const float* proj_out_w = (const float*)d_in[21];
    const float* proj_out_b = (const float*)d_in[22];
    float* out = (float*)d_out;

    float *h_, *t3_, *hp_;
    __half *xp_, *t2h_, *yh_;
    __half *wqkvH_, *ffw1H_, *ffw2H_, *woutH_, *wAH_, *wBH_, *wtH_;
    cudaGetSymbolAddress((void**)&h_,     g_h);
    cudaGetSymbolAddress((void**)&t3_,    g_t3);
    cudaGetSymbolAddress((void**)&hp_,    g_hp);
    cudaGetSymbolAddress((void**)&xp_,    g_xp);
    cudaGetSymbolAddress((void**)&t2h_,   g_t2h);
    cudaGetSymbolAddress((void**)&yh_,    g_yh);
    cudaGetSymbolAddress((void**)&wqkvH_, g_wqkvH);
    cudaGetSymbolAddress((void**)&ffw1H_, g_ffw1H);
    cudaGetSymbolAddress((void**)&ffw2H_, g_ffw2H);
    cudaGetSymbolAddress((void**)&woutH_, g_woutH);
    cudaGetSymbolAddress((void**)&wAH_,   g_wAH);
    cudaGetSymbolAddress((void**)&wBH_,   g_wBH);
    cudaGetSymbolAddress((void**)&wtH_,   g_wtH);

    // Fused weight prep
    prep_all<<<PRE4, 256>>>(wqkv, ffw1, ffw2, wout, proj_in_w, proj_out_w, local_w,
                            wqkvH_, ffw1H_, ffw2H_, woutH_, wAH_, wBH_, wtH_);

    // 1. pool -> xp (half)
    pool_kernel<<<NB * NC, 256>>>(x, xp_);
    // 2. h = xp @ wAH + proj_in_b   (M=4096, N=384, K=512) -> fp32
    hgemm<0, false, 0, 0><<<dim3(3, 64), 256>>>(
        xp_, wAH_, proj_in_b, nullptr, h_, NROWS, ND, NC);
    // 3. norm_in (fp32 residual)
    ln_kernel<0><<<NROWS / 8, 256>>>(h_, norm_in_g, norm_in_b, h_);

    for (int i = 0; i < 2; i++) {
        ln_kernel<1><<<NROWS / 8, 256>>>(h_, ln1_g + i * ND, ln1_b + i * ND, t2h_);
        hgemm<0, false, 1, 0><<<dim3(12, 64), 256>>>(
            t2h_, wqkvH_ + (size_t)i * ND * NFF, nullptr, nullptr, yh_, NROWS, NFF, ND);
        attn_kernel<<<NB * NHEADS, 256>>>(yh_, rf + i * NDH * NDH, xp_);
        hgemm<0, true, 0, 0><<<dim3(3, 64), 256>>>(
            xp_, woutH_ + (size_t)i * NINNER * ND, bout + i * ND, h_, h_, NROWS, ND, NINNER);
        ln_kernel<1><<<NROWS / 8, 256>>>(h_, ln2_g + i * ND, ln2_b + i * ND, t2h_);
        hgemm<1, false, 1, 0><<<dim3(12, 64), 256>>>(
            t2h_, ffw1H_ + (size_t)i * ND * NFF, ffb1 + i * NFF, nullptr, yh_, NROWS, NFF, ND);
        hgemm<0, true, 0, 0><<<dim3(3, 64), 256>>>(
            yh_, ffw2H_ + (size_t)i * NFF * ND, ffb2 + i * ND, h_, h_, NROWS, ND, NFF);
    }

    // local conv as one GEMM with fused gather: t3 = h + convA(h) @ wtH + local_b
    hgemm<0, true, 0, 1><<<dim3(3, 64), 256>>>(
        (const void*)h_, wtH_, local_b, h_, t3_, NROWS, ND, 3 * ND);
    // norm_out -> half (feeds proj_out)
    ln_kernel<1><<<NROWS / 8, 256>>>(t3_, norm_out_g, norm_out_b, t2h_);
    // hp = t2h @ wBH + proj_out_b   (M=4096, N=512, K=384) -> fp32
    hgemm<0, false, 0, 0><<<dim3(4, 64), 256>>>(
        t2h_, wBH_, proj_out_b, nullptr, hp_, NROWS, NC, ND);
    // interp + residual with x
    final_kernel<<<(NB * NC * NL) / 256, 256>>>(hp_, x, out);
}

// round 11
// speedup vs baseline: 1.0428x; 1.0428x over previous
#include <cuda_runtime.h>
#include <cuda_fp16.h>
#include <cstdint>
#include <math.h>

// Problem constants
#define NB   16
#define NC   512
#define NL   4096
#define ND   384
#define NTOK 256
#define NROWS 4096      // NB*NTOK
#define NINNER 512
#define NFF  1536
#define NHEADS 8
#define NDH  64

// ---------------------------------------------------------------------------
// Scratch (device globals; allocation-free)
// ---------------------------------------------------------------------------
__device__ alignas(16) float  g_h  [NROWS*ND];      // residual stream (fp32)
__device__ alignas(16) float  g_t3 [NROWS*ND];      // conv out (fp32)
__device__ alignas(16) float  g_hp [NROWS*NC];      // hp for final (fp32)
__device__ alignas(16) __half g_xp [NROWS*NINNER];  // pool out / attn out (half)
__device__ alignas(16) __half g_t2h[NROWS*ND];      // LN outputs (half)
__device__ alignas(16) __half g_yh [NROWS*NFF];     // qkv / ff1 (half)
// half weights
__device__ alignas(16) __half g_wqkvH[2*ND*NFF];    // [K=384][N=1536]
__device__ alignas(16) __half g_ffw1H[2*ND*NFF];    // [K=384][N=1536]
__device__ alignas(16) __half g_ffw2H[2*NFF*ND];    // [K=1536][N=384]
__device__ alignas(16) __half g_woutH[2*NINNER*ND]; // [K=512][N=384]
__device__ alignas(16) __half g_wAH[NC*ND];         // proj_in^T  [512][384]
__device__ alignas(16) __half g_wBH[ND*NC];         // proj_out^T [384][512]
__device__ alignas(16) __half g_wtH[3*ND*ND];       // conv [K=1152][N=384]

__device__ __forceinline__ float gelu_exact(float v) { return v * normcdff(v); }

__device__ __forceinline__ float4 ld4h(const __half* p) {
    uint2 u = *(const uint2*)p;
    float2 fa = __half22float2(*(__half2*)&u.x);
    float2 fb = __half22float2(*(__half2*)&u.y);
    return make_float4(fa.x, fa.y, fb.x, fb.y);
}
__device__ __forceinline__ void st4h(__half* p, float4 v) {
    uint2 u;
    *(__half2*)&u.x = __floats2half2_rn(v.x, v.y);
    *(__half2*)&u.y = __floats2half2_rn(v.z, v.w);
    *(uint2*)p = u;
}

__device__ __forceinline__ void mma_f16(float (&d)[4], const unsigned (&a)[4],
                                        const unsigned (&b)[2]) {
    asm volatile(
        "mma.sync.aligned.m16n8k16.row.col.f32.f16.f16.f32 "
        "{%0,%1,%2,%3}, {%4,%5,%6,%7}, {%8,%9}, {%0,%1,%2,%3};\n"
        : "+f"(d[0]), "+f"(d[1]), "+f"(d[2]), "+f"(d[3])
        : "r"(a[0]), "r"(a[1]), "r"(a[2]), "r"(a[3]), "r"(b[0]), "r"(b[1]));
}

__device__ __forceinline__ void ldsm4(unsigned (&r)[4], uint32_t addr) {
    asm volatile("ldmatrix.sync.aligned.m8n8.x4.shared.b16 {%0,%1,%2,%3}, [%4];"
                 : "=r"(r[0]), "=r"(r[1]), "=r"(r[2]), "=r"(r[3]) : "r"(addr));
}
__device__ __forceinline__ void ldsm4t(unsigned& r0, unsigned& r1,
                                       unsigned& r2, unsigned& r3, uint32_t addr) {
    asm volatile("ldmatrix.sync.aligned.m8n8.x4.trans.shared.b16 {%0,%1,%2,%3}, [%4];"
                 : "=r"(r0), "=r"(r1), "=r"(r2), "=r"(r3) : "r"(addr));
}

// ---------------------------------------------------------------------------
// fp16 mma.sync GEMM. BM=MT*64, BN=128, BK=32. 256 threads = 8 warps (4x2);
// warp tile (MT*16)x64. Register-staged double buffer, ONE sync per K-slice
// (safe: storing buf_s at iter s+2 requires passing sync(s+1), which every
// warp reaches only after completing mma(s)).
// LDA=40 halves (80B rows), LDB=136 (272B): 16B-aligned, conflict-free.
// CONV=1: A gathered on-the-fly from fp32 h with +-1 token shift (MT=1 only).
// OUTH=1: half output. ACC adds fp32 Cin. ACT=1: exact GELU.
// ---------------------------------------------------------------------------
template<int MT, int ACT, bool ACC, int OUTH, int CONV>
__global__ __launch_bounds__(256, 2) void hgemm(
    const void* __restrict__ Av, const __half* __restrict__ Bw,
    const float* __restrict__ bias, const float* __restrict__ Cin,
    void* __restrict__ Cv, int M, int N, int K)
{
    constexpr int BM  = MT * 64;
    constexpr int LDA = 40;
    constexpr int LDB = 136;

    __shared__ alignas(16) __half As[2][BM * LDA];
    __shared__ alignas(16) __half Bs[2][32 * LDB];

    const int tid = threadIdx.x;
    const int warp = tid >> 5, lane = tid & 31;
    const int wr = warp >> 1, wc = warp & 1;      // 4 x 2 warps
    const int wm = wr * (MT * 16), wn = wc * 64;
    const int m0 = blockIdx.y * BM, n0 = blockIdx.x * 128;
    const int NS = K >> 5;

    const __half* A  = (const __half*)Av;
    const float*  Hc = (const float*)Av;

    float acc[MT][8][4];
#pragma unroll
    for (int mt = 0; mt < MT; mt++)
#pragma unroll
        for (int nt = 0; nt < 8; nt++)
#pragma unroll
            for (int i = 0; i < 4; i++) acc[mt][nt][i] = 0.f;

    uint4 stA[MT], stB[2];

    auto loadA = [&](int s) {
#pragma unroll
        for (int i = 0; i < MT; i++) {
            int lin = tid + i * 256;
            int row = lin >> 2, ch = lin & 3;
            if (CONV) {
                int k0 = s * 32 + ch * 8;
                int seg = k0 / ND;
                int col = k0 - seg * ND;
                int gr = m0 + row;
                int n = gr & 255;
                bool ok = (seg == 1) || (seg == 0 && n > 0) || (seg == 2 && n < 255);
                float4 f0 = make_float4(0.f, 0.f, 0.f, 0.f), f1 = f0;
                if (ok) {
                    const float* p = Hc + (size_t)(gr + seg - 1) * ND + col;
                    f0 = *(const float4*)p;
                    f1 = *(const float4*)(p + 4);
                }
                uint4 u;
                *(__half2*)&u.x = __floats2half2_rn(f0.x, f0.y);
                *(__half2*)&u.y = __floats2half2_rn(f0.z, f0.w);
                *(__half2*)&u.z = __floats2half2_rn(f1.x, f1.y);
                *(__half2*)&u.w = __floats2half2_rn(f1.z, f1.w);
                stA[i] = u;
            } else {
                stA[i] = *(const uint4*)(A + (size_t)(m0 + row) * K + s * 32 + ch * 8);
            }
        }
    };
    auto loadB = [&](int s) {
#pragma unroll
        for (int i = 0; i < 2; i++) {
            int lin = tid + i * 256;
            int row = lin >> 4, c8 = (lin & 15) << 3;
            stB[i] = *(const uint4*)(Bw + (size_t)(s * 32 + row) * N + n0 + c8);
        }
    };

    loadA(0); loadB(0);

    for (int s = 0; s < NS; s++) {
        const int buf = s & 1;
#pragma unroll
        for (int i = 0; i < MT; i++) {
            int lin = tid + i * 256;
            int row = lin >> 2, ch = lin & 3;
            *(uint4*)&As[buf][row * LDA + ch * 8] = stA[i];
        }
#pragma unroll
        for (int i = 0; i < 2; i++) {
            int lin = tid + i * 256;
            int row = lin >> 4, c8 = (lin & 15) << 3;
            *(uint4*)&Bs[buf][row * LDB + c8] = stB[i];
        }
        // issue next-slice global loads before the barrier (overlap)
        if (s + 1 < NS) { loadA(s + 1); loadB(s + 1); }
        __syncthreads();

#pragma unroll
        for (int ks = 0; ks < 2; ks++) {
            unsigned af[MT][4], bf[8][2];
#pragma unroll
            for (int mt = 0; mt < MT; mt++) {
                uint32_t aa = (uint32_t)__cvta_generic_to_shared(
                    &As[buf][(wm + mt * 16 + (lane & 15)) * LDA + ks * 16 + ((lane >> 4) << 3)]);
                ldsm4(af[mt], aa);
            }
#pragma unroll
            for (int np = 0; np < 4; np++) {
                uint32_t ba = (uint32_t)__cvta_generic_to_shared(
                    &Bs[buf][(ks * 16 + (lane & 15)) * LDB + wn + np * 16 + ((lane >> 4) << 3)]);
                ldsm4t(bf[np * 2][0], bf[np * 2][1], bf[np * 2 + 1][0], bf[np * 2 + 1][1], ba);
            }
#pragma unroll
            for (int mt = 0; mt < MT; mt++)
#pragma unroll
                for (int nt = 0; nt < 8; nt++)
                    mma_f16(acc[mt][nt], af[mt], bf[nt]);
        }
    }

    // epilogue
#pragma unroll
    for (int mt = 0; mt < MT; mt++) {
#pragma unroll
        for (int nt = 0; nt < 8; nt++) {
#pragma unroll
            for (int half_i = 0; half_i < 2; half_i++) {
                const int row = m0 + wm + mt * 16 + (lane >> 2) + half_i * 8;
                const int col = n0 + wn + nt * 8 + (lane & 3) * 2;
                float2 r;
                r.x = acc[mt][nt][half_i * 2];
                r.y = acc[mt][nt][half_i * 2 + 1];
                if (bias) { r.x += bias[col]; r.y += bias[col + 1]; }
                if (ACT == 1) { r.x = gelu_exact(r.x); r.y = gelu_exact(r.y); }
                if (ACC) {
                    const float* cp = Cin + (size_t)row * N + col;
                    r.x += cp[0]; r.y += cp[1];
                }
                if (OUTH) {
                    __half2* cp = (__half2*)((__half*)Cv + (size_t)row * N + col);
                    *cp = __floats2half2_rn(r.x, r.y);
                } else {
                    *(float2*)((float*)Cv + (size_t)row * N + col) = r;
                }
            }
        }
    }
}

// ---------------------------------------------------------------------------
// Fused weight prep: converts/transposes ALL weights in one launch.
//  blocks [0, 3840): fp32->half copies (wqkv, ffw1, ffw2, wout)
//  blocks [3840, 4032): transpose proj_in_w -> wAH
//  blocks [4032, 4224): transpose proj_out_w -> wBH
//  blocks [4224, 5952): conv weight reshape -> wtH
// ---------------------------------------------------------------------------
#define WP_N1 (2*ND*NFF/4)      // 294912
#define WP_N4 (2*NINNER*ND/4)   // 98304
#define PRE1 3840
#define PRE2 (PRE1 + 192)
#define PRE3 (PRE2 + 192)
#define PRE4 (PRE3 + 1728)
__global__ __launch_bounds__(256) void prep_all(
    const float* __restrict__ wqkv, const float* __restrict__ ffw1,
    const float* __restrict__ ffw2, const float* __restrict__ wout,
    const float* __restrict__ proj_in_w, const float* __restrict__ proj_out_w,
    const float* __restrict__ local_w,
    __half* __restrict__ o1, __half* __restrict__ o2,
    __half* __restrict__ o3, __half* __restrict__ o4,
    __half* __restrict__ wAH, __half* __restrict__ wBH, __half* __restrict__ wtH)
{
    __shared__ float tt[32][33];
    const int blk = blockIdx.x, t = threadIdx.x;
    if (blk < PRE1) {
        int i = blk * 256 + t;
        const float* src; __half* dst; int j;
        if (i < WP_N1)          { src = wqkv; dst = o1; j = i; }
        else if (i < 2 * WP_N1) { src = ffw1; dst = o2; j = i - WP_N1; }
        else if (i < 3 * WP_N1) { src = ffw2; dst = o3; j = i - 2 * WP_N1; }
        else                    { src = wout; dst = o4; j = i - 3 * WP_N1; }
        st4h(dst + (size_t)j * 4, ((const float4*)src)[j]);
    } else if (blk < PRE3) {
        int R, Cc, bx, by;
        const float* src; __half* dst;
        if (blk < PRE2) { int b = blk - PRE1; R = ND; Cc = NC; bx = b % 16; by = b / 16; src = proj_in_w;  dst = wAH; }
        else            { int b = blk - PRE2; R = NC; Cc = ND; bx = b % 12; by = b / 12; src = proj_out_w; dst = wBH; }
        int tx = t & 31, ty = t >> 5;
        int c = bx * 32 + tx, r = by * 32 + ty;
#pragma unroll
        for (int i = 0; i < 32; i += 8)
            tt[ty + i][tx] = src[(size_t)(r + i) * Cc + c];
        __syncthreads();
        int co = by * 32 + tx, ro = bx * 32 + ty;
#pragma unroll
        for (int i = 0; i < 32; i += 8)
            dst[(size_t)(ro + i) * R + co] = __float2half(tt[tx][ty + i]);
    } else {
        int idx = (blk - PRE3) * 256 + t;
        int krow = idx / ND, dout = idx - krow * ND;
        int k = krow / ND, din = krow - k * ND;
        wtH[idx] = __float2half(local_w[(dout * ND + din) * 3 + k]);
    }
}

// ---------------------------------------------------------------------------
// Pool: x[B,C,L] -> xpT[(b*256+n), c] (half), mean over windows of 16
// ---------------------------------------------------------------------------
__global__ __launch_bounds__(256) void pool_kernel(const float* __restrict__ x,
                                                   __half* __restrict__ xpT)
{
    int bc = blockIdx.x;
    int b = bc >> 9, c = bc & 511;
    const float4* src = (const float4*)(x + (size_t)bc * NL) + threadIdx.x * 4;
    float s = 0.f;
#pragma unroll
    for (int j = 0; j < 4; j++) {
        float4 v = src[j];
        s += v.x + v.y + v.z + v.w;
    }
    xpT[((size_t)(b * NTOK + threadIdx.x)) * NC + c] = __float2half(s * (1.f / 16.f));
}

// ---------------------------------------------------------------------------
// LayerNorm over last dim (384). Warp per row. OUTH: half output.
// ---------------------------------------------------------------------------
template<int OUTH>
__global__ __launch_bounds__(256) void ln_kernel(const float* __restrict__ in,
                                                 const float* __restrict__ g,
                                                 const float* __restrict__ b,
                                                 void* __restrict__ outv)
{
    const int wid = threadIdx.x >> 5, lane = threadIdx.x & 31;
    const int row = blockIdx.x * 8 + wid;
    const float* xr = in + (size_t)row * ND;
    float4 v0 = *(const float4*)(xr + lane * 4);
    float4 v1 = *(const float4*)(xr + 128 + lane * 4);
    float4 v2 = *(const float4*)(xr + 256 + lane * 4);
    float s = v0.x + v0.y + v0.z + v0.w + v1.x + v1.y + v1.z + v1.w
            + v2.x + v2.y + v2.z + v2.w;
    float q = v0.x*v0.x + v0.y*v0.y + v0.z*v0.z + v0.w*v0.w
            + v1.x*v1.x + v1.y*v1.y + v1.z*v1.z + v1.w*v1.w
            + v2.x*v2.x + v2.y*v2.y + v2.z*v2.z + v2.w*v2.w;
#pragma unroll
    for (int o = 16; o; o >>= 1) {
        s += __shfl_xor_sync(0xFFFFFFFFu, s, o);
        q += __shfl_xor_sync(0xFFFFFFFFu, q, o);
    }
    const float mean = s * (1.f / ND);
    const float var  = q * (1.f / ND) - mean * mean;
    const float inv  = rsqrtf(var + 1e-5f);
#pragma unroll
    for (int j = 0; j < 3; j++) {
        int col = j * 128 + lane * 4;
        float4 v = (j == 0) ? v0 : (j == 1) ? v1 : v2;
        float4 gg = *(const float4*)(g + col);
        float4 bb = *(const float4*)(b + col);
        float4 r;
        r.x = (v.x - mean) * inv * gg.x + bb.x;
        r.y = (v.y - mean) * inv * gg.y + bb.y;
        r.z = (v.z - mean) * inv * gg.z + bb.z;
        r.w = (v.w - mean) * inv * gg.w + bb.w;
        if (OUTH) st4h((__half*)outv + (size_t)row * ND + col, r);
        else      *(float4*)((float*)outv + (size_t)row * ND + col) = r;
    }
}

// ---------------------------------------------------------------------------
// Linear attention per (b,h); half in (qkv), half out. Internal fp32.
// ---------------------------------------------------------------------------
__device__ __forceinline__ void r1u(float (&acc)[4][4], float a0, float a1,
                                    float a2, float a3, const float4 b)
{
    acc[0][0] += a0 * b.x; acc[0][1] += a0 * b.y; acc[0][2] += a0 * b.z; acc[0][3] += a0 * b.w;
    acc[1][0] += a1 * b.x; acc[1][1] += a1 * b.y; acc[1][2] += a1 * b.z; acc[1][3] += a1 * b.w;
    acc[2][0] += a2 * b.x; acc[2][1] += a2 * b.y; acc[2][2] += a2 * b.z; acc[2][3] += a2 * b.w;
    acc[3][0] += a3 * b.x; acc[3][1] += a3 * b.y; acc[3][2] += a3 * b.z; acc[3][3] += a3 * b.w;
}

__global__ __launch_bounds__(256) void attn_kernel(const __half* __restrict__ qkv,
                                                   const float* __restrict__ rf,
                                                   __half* __restrict__ o)
{
    __shared__ float rf_s[4096];
    __shared__ float bufA[4096];
    __shared__ float bufB[4096];
    const int tid = threadIdx.x;
    const int bh = blockIdx.x;
    const int b = bh >> 3, h = bh & 7;
    const int tq = tid >> 4, tr = tid & 15;

#pragma unroll
    for (int j = 0; j < 4; j++)
        ((float4*)rf_s)[tid + j * 256] = ((const float4*)rf)[tid + j * 256];

    const __half* base = qkv + (size_t)b * NTOK * NFF + h * NDH;

    float kv[4][4];
#pragma unroll
    for (int i = 0; i < 4; i++)
#pragma unroll
        for (int j = 0; j < 4; j++) kv[i][j] = 0.f;

    for (int n0 = 0; n0 < NTOK; n0 += 64) {
        __syncthreads();
#pragma unroll
        for (int j = 0; j < 4; j++) {
            int lin = tid + j * 256;
            int rowi = lin >> 4, c4 = (lin & 15) << 2;
            const __half* rp = base + (size_t)(n0 + rowi) * NFF;
            float4 kk = ld4h(rp + NINNER + c4);
            kk.x = fmaxf(kk.x, 0.f); kk.y = fmaxf(kk.y, 0.f);
            kk.z = fmaxf(kk.z, 0.f); kk.w = fmaxf(kk.w, 0.f);
            *(float4*)&bufA[rowi * 64 + c4] = kk;
            *(float4*)&bufB[rowi * 64 + c4] = ld4h(rp + 2 * NINNER + c4);
        }
        __syncthreads();
#pragma unroll 8
        for (int nn = 0; nn < 64; nn++) {
            float4 ka = *(const float4*)&bufA[nn * 64 + tq * 4];
            float4 vb = *(const float4*)&bufB[nn * 64 + tr * 4];
            r1u(kv, ka.x, ka.y, ka.z, ka.w, vb);
        }
    }
    __syncthreads();
#pragma unroll
    for (int i = 0; i < 4; i++) {
        float4 v = make_float4(kv[i][0], kv[i][1], kv[i][2], kv[i][3]);
        *(float4*)&bufA[(tq * 4 + i) * 64 + tr * 4] = v;
    }
    __syncthreads();

    float w1[4][4];
#pragma unroll
    for (int i = 0; i < 4; i++)
#pragma unroll
        for (int j = 0; j < 4; j++) w1[i][j] = 0.f;
#pragma unroll 8
    for (int dk = 0; dk < 64; dk++) {
        float4 rm = *(const float4*)&rf_s[dk * 64 + tq * 4];
        float4 kd = *(const float4*)&bufA[dk * 64 + tr * 4];
        r1u(w1, rm.x, rm.y, rm.z, rm.w, kd);
    }
    __syncthreads();
#pragma unroll
    for (int i = 0; i < 4; i++) {
        float4 v = make_float4(w1[i][0], w1[i][1], w1[i][2], w1[i][3]);
        *(float4*)&bufB[(tq * 4 + i) * 64 + tr * 4] = v;
    }
    __syncthreads();

    float w2[4][4];
#pragma unroll
    for (int i = 0; i < 4; i++)
#pragma unroll
        for (int j = 0; j < 4; j++) w2[i][j] = 0.f;
#pragma unroll 8
    for (int m = 0; m < 64; m++) {
        float4 wd = *(const float4*)&bufB[m * 64 + tr * 4];
        float r0 = rf_s[(tq * 4 + 0) * 64 + m];
        float r1 = rf_s[(tq * 4 + 1) * 64 + m];
        float r2 = rf_s[(tq * 4 + 2) * 64 + m];
        float r3 = rf_s[(tq * 4 + 3) * 64 + m];
        r1u(w2, r0, r1, r2, r3, wd);
    }
    __syncthreads();
#pragma unroll
    for (int i = 0; i < 4; i++) {
        float4 v = make_float4(w2[i][0], w2[i][1], w2[i][2], w2[i][3]);
        *(float4*)&bufA[(tq * 4 + i) * 64 + tr * 4] = v;
    }
    __syncthreads();

    for (int n0 = 0; n0 < NTOK; n0 += 64) {
#pragma unroll
        for (int j = 0; j < 4; j++) {
            int lin = tid + j * 256;
            int rowi = lin >> 4, c4 = (lin & 15) << 2;
            const __half* rp = base + (size_t)(n0 + rowi) * NFF;
            float4 qq = ld4h(rp + c4);
            qq.x = fmaxf(qq.x, 0.f) * 0.125f; qq.y = fmaxf(qq.y, 0.f) * 0.125f;
            qq.z = fmaxf(qq.z, 0.f) * 0.125f; qq.w = fmaxf(qq.w, 0.f) * 0.125f;
            *(float4*)&bufB[rowi * 64 + c4] = qq;
        }
        __syncthreads();
        float oc[4][4];
#pragma unroll
        for (int i = 0; i < 4; i++)
#pragma unroll
            for (int j = 0; j < 4; j++) oc[i][j] = 0.f;
#pragma unroll 8
        for (int dq = 0; dq < 64; dq++) {
            float4 wd = *(const float4*)&bufA[dq * 64 + tr * 4];
            float q0 = bufB[(tq * 4 + 0) * 64 + dq];
            float q1 = bufB[(tq * 4 + 1) * 64 + dq];
            float q2 = bufB[(tq * 4 + 2) * 64 + dq];
            float q3 = bufB[(tq * 4 + 3) * 64 + dq];
            r1u(oc, q0, q1, q2, q3, wd);
        }
#pragma unroll
        for (int i = 0; i < 4; i++) {
            st4h(o + (size_t)(b * NTOK + n0 + tq * 4 + i) * NINNER + h * NDH + tr * 4,
                 make_float4(oc[i][0], oc[i][1], oc[i][2], oc[i][3]));
        }
        __syncthreads();
    }
}

// ---------------------------------------------------------------------------
// Final: out[b,c,l] = interp(hp)[b,c,l] + x[b,c,l]
// ---------------------------------------------------------------------------
__global__ __launch_bounds__(256) void final_kernel(const float* __restrict__ hp,
                                                    const float* __restrict__ x,
                                                    float* __restrict__ out)
{
    size_t idx = (size_t)blockIdx.x * 256 + threadIdx.x;
    int l = (int)(idx & 4095);
    int c = (int)((idx >> 12) & 511);
    int b = (int)(idx >> 21);
    float src = fmaxf((l + 0.5f) * 0.0625f - 0.5f, 0.f);
    int i0 = (int)src;
    float w = src - (float)i0;
    int i1 = min(i0 + 1, 255);
    float v0 = hp[(size_t)(b * NTOK + i0) * NC + c];
    float v1 = hp[(size_t)(b * NTOK + i1) * NC + c];
    out[idx] = v0 * (1.f - w) + v1 * w + x[idx];
}

// ---------------------------------------------------------------------------
// Host orchestration
// ---------------------------------------------------------------------------
extern "C" void kernel_launch(void* const* d_in, const int* in_sizes, int n_in,
                              void* d_out, int out_size)
{
    const float* x          = (const float*)d_in[0];
    const float* proj_in_w  = (const float*)d_in[1];
    const float* proj_in_b  = (const float*)d_in[2];
    const float* norm_in_g  = (const float*)d_in[3];
    const float* norm_in_b  = (const float*)d_in[4];
    const float* ln1_g      = (const float*)d_in[5];
    const float* ln1_b      = (const float*)d_in[6];
    const float* wqkv       = (const float*)d_in[7];
    const float* rf         = (const float*)d_in[8];
    const float* wout       = (const float*)d_in[9];
    const float* bout       = (const float*)d_in[10];
    const float* ln2_g      = (const float*)d_in[11];
    const float* ln2_b      = (const float*)d_in[12];
    const float* ffw1       = (const float*)d_in[13];
    const float* ffb1       = (const float*)d_in[14];
    const float* ffw2       = (const float*)d_in[15];
    const float* ffb2       = (const float*)d_in[16];
    const float* local_w    = (const float*)d_in[17];
    const float* local_b    = (const float*)d_in[18];
    const float* norm_out_g = (const float*)d_in[19];
    const float* norm_out_b = (const float*)d_in[20];
    const float* proj_out_w = (const float*)d_in[21];
    const float* proj_out_b = (const float*)d_in[22];
    float* out = (float*)d_out;

    float *h_, *t3_, *hp_;
    __half *xp_, *t2h_, *yh_;
    __half *wqkvH_, *ffw1H_, *ffw2H_, *woutH_, *wAH_, *wBH_, *wtH_;
    cudaGetSymbolAddress((void**)&h_,     g_h);
    cudaGetSymbolAddress((void**)&t3_,    g_t3);
    cudaGetSymbolAddress((void**)&hp_,    g_hp);
    cudaGetSymbolAddress((void**)&xp_,    g_xp);
    cudaGetSymbolAddress((void**)&t2h_,   g_t2h);
    cudaGetSymbolAddress((void**)&yh_,    g_yh);
    cudaGetSymbolAddress((void**)&wqkvH_, g_wqkvH);
    cudaGetSymbolAddress((void**)&ffw1H_, g_ffw1H);
    cudaGetSymbolAddress((void**)&ffw2H_, g_ffw2H);
    cudaGetSymbolAddress((void**)&woutH_, g_woutH);
    cudaGetSymbolAddress((void**)&wAH_,   g_wAH);
    cudaGetSymbolAddress((void**)&wBH_,   g_wBH);
    cudaGetSymbolAddress((void**)&wtH_,   g_wtH);

    // Fused weight prep
    prep_all<<<PRE4, 256>>>(wqkv, ffw1, ffw2, wout, proj_in_w, proj_out_w, local_w,
                            wqkvH_, ffw1H_, ffw2H_, woutH_, wAH_, wBH_, wtH_);

    // 1. pool -> xp (half)
    pool_kernel<<<NB * NC, 256>>>(x, xp_);
    // 2. h = xp @ wAH + proj_in_b   (M=4096, N=384, K=512) -> fp32
    hgemm<1, 0, false, 0, 0><<<dim3(3, 64), 256>>>(
        xp_, wAH_, proj_in_b, nullptr, h_, NROWS, ND, NC);
    // 3. norm_in (fp32 residual)
    ln_kernel<0><<<NROWS / 8, 256>>>(h_, norm_in_g, norm_in_b, h_);

    for (int i = 0; i < 2; i++) {
        ln_kernel<1><<<NROWS / 8, 256>>>(h_, ln1_g + i * ND, ln1_b + i * ND, t2h_);
        hgemm<2, 0, false, 1, 0><<<dim3(12, 32), 256>>>(
            t2h_, wqkvH_ + (size_t)i * ND * NFF, nullptr, nullptr, yh_, NROWS, NFF, ND);
        attn_kernel<<<NB * NHEADS, 256>>>(yh_, rf + i * NDH * NDH, xp_);
        hgemm<1, 0, true, 0, 0><<<dim3(3, 64), 256>>>(
            xp_, woutH_ + (size_t)i * NINNER * ND, bout + i * ND, h_, h_, NROWS, ND, NINNER);
        ln_kernel<1><<<NROWS / 8, 256>>>(h_, ln2_g + i * ND, ln2_b + i * ND, t2h_);
        hgemm<2, 1, false, 1, 0><<<dim3(12, 32), 256>>>(
            t2h_, ffw1H_ + (size_t)i * ND * NFF, ffb1 + i * NFF, nullptr, yh_, NROWS, NFF, ND);
        hgemm<1, 0, true, 0, 0><<<dim3(3, 64), 256>>>(
            yh_, ffw2H_ + (size_t)i * NFF * ND, ffb2 + i * ND, h_, h_, NROWS, ND, NFF);
    }

    // local conv as one GEMM with fused gather: t3 = h + convA(h) @ wtH + local_b
    hgemm<1, 0, true, 0, 1><<<dim3(3, 64), 256>>>(
        (const void*)h_, wtH_, local_b, h_, t3_, NROWS, ND, 3 * ND);
    // norm_out -> half (feeds proj_out)
    ln_kernel<1><<<NROWS / 8, 256>>>(t3_, norm_out_g, norm_out_b, t2h_);
    // hp = t2h @ wBH + proj_out_b   (M=4096, N=512, K=384) -> fp32
    hgemm<1, 0, false, 0, 0><<<dim3(4, 64), 256>>>(
        t2h_, wBH_, proj_out_b, nullptr, hp_, NROWS, NC, ND);
    // interp + residual with x
    final_kernel<<<(NB * NC * NL) / 256, 256>>>(hp_, x, out);
}

// round 14
// speedup vs baseline: 1.0999x; 1.0547x over previous
#include <cuda_runtime.h>
#include <cuda_fp16.h>
#include <cstdint>
#include <math.h>

// Problem constants
#define NB   16
#define NC   512
#define NL   4096
#define ND   384
#define NTOK 256
#define NROWS 4096      // NB*NTOK
#define NINNER 512
#define NFF  1536
#define NHEADS 8
#define NDH  64

// ---------------------------------------------------------------------------
// Scratch (device globals; allocation-free)
// ---------------------------------------------------------------------------
__device__ alignas(16) float  g_h  [NROWS*ND];      // residual stream (fp32)
__device__ alignas(16) float  g_t3 [NROWS*ND];      // conv out (fp32)
__device__ alignas(16) float  g_hp [NROWS*NC];      // hp for final (fp32)
__device__ alignas(16) __half g_xp [NROWS*NINNER];  // pool out / attn out (half)
__device__ alignas(16) __half g_t2h[NROWS*ND];      // LN outputs (half)
__device__ alignas(16) __half g_yh [NROWS*NFF];     // qkv / ff1 (half)
// half weights
__device__ alignas(16) __half g_wqkvH[2*ND*NFF];    // [K=384][N=1536]
__device__ alignas(16) __half g_ffw1H[2*ND*NFF];    // [K=384][N=1536]
__device__ alignas(16) __half g_ffw2H[2*NFF*ND];    // [K=1536][N=384]
__device__ alignas(16) __half g_woutH[2*NINNER*ND]; // [K=512][N=384]
__device__ alignas(16) __half g_wAH[NC*ND];         // proj_in^T  [512][384]
__device__ alignas(16) __half g_wBH[ND*NC];         // proj_out^T [384][512]
__device__ alignas(16) __half g_wtH[3*ND*ND];       // conv [K=1152][N=384]

__device__ __forceinline__ float gelu_exact(float v) { return v * normcdff(v); }

__device__ __forceinline__ float4 ld4h(const __half* p) {
    uint2 u = *(const uint2*)p;
    float2 fa = __half22float2(*(__half2*)&u.x);
    float2 fb = __half22float2(*(__half2*)&u.y);
    return make_float4(fa.x, fa.y, fb.x, fb.y);
}
__device__ __forceinline__ void st4h(__half* p, float4 v) {
    uint2 u;
    *(__half2*)&u.x = __floats2half2_rn(v.x, v.y);
    *(__half2*)&u.y = __floats2half2_rn(v.z, v.w);
    *(uint2*)p = u;
}

__device__ __forceinline__ void mma_f16(float (&d)[4], const unsigned (&a)[4],
                                        const unsigned (&b)[2]) {
    asm volatile(
        "mma.sync.aligned.m16n8k16.row.col.f32.f16.f16.f32 "
        "{%0,%1,%2,%3}, {%4,%5,%6,%7}, {%8,%9}, {%0,%1,%2,%3};\n"
        : "+f"(d[0]), "+f"(d[1]), "+f"(d[2]), "+f"(d[3])
        : "r"(a[0]), "r"(a[1]), "r"(a[2]), "r"(a[3]), "r"(b[0]), "r"(b[1]));
}

__device__ __forceinline__ void ldsm4(unsigned (&r)[4], uint32_t addr) {
    asm volatile("ldmatrix.sync.aligned.m8n8.x4.shared.b16 {%0,%1,%2,%3}, [%4];"
                 : "=r"(r[0]), "=r"(r[1]), "=r"(r[2]), "=r"(r[3]) : "r"(addr));
}
__device__ __forceinline__ void ldsm4t(unsigned& r0, unsigned& r1,
                                       unsigned& r2, unsigned& r3, uint32_t addr) {
    asm volatile("ldmatrix.sync.aligned.m8n8.x4.trans.shared.b16 {%0,%1,%2,%3}, [%4];"
                 : "=r"(r0), "=r"(r1), "=r"(r2), "=r"(r3) : "r"(addr));
}

// ---------------------------------------------------------------------------
// fp16 mma.sync GEMM. BM=MT*64, BN=128, BK=32. 256 threads = 8 warps (4x2);
// warp tile (MT*16)x64. Register-staged double buffer, ONE sync per K-slice
// (safe: storing buf_s at iter s+2 requires passing sync(s+1), which every
// warp reaches only after completing mma(s)).
// LDA=40 halves (80B rows), LDB=136 (272B): 16B-aligned, conflict-free.
// CONV=1: A gathered on-the-fly from fp32 h with +-1 token shift (MT=1 only).
// OUTH=1: half output. ACC adds fp32 Cin. ACT=1: exact GELU.
// ---------------------------------------------------------------------------
template<int MT, int ACT, bool ACC, int OUTH, int CONV>
__global__ __launch_bounds__(256, 2) void hgemm(
    const void* __restrict__ Av, const __half* __restrict__ Bw,
    const float* __restrict__ bias, const float* __restrict__ Cin,
    void* __restrict__ Cv, int M, int N, int K)
{
    constexpr int BM  = MT * 64;
    constexpr int LDA = 40;
    constexpr int LDB = 136;

    __shared__ alignas(16) __half As[2][BM * LDA];
    __shared__ alignas(16) __half Bs[2][32 * LDB];

    const int tid = threadIdx.x;
    const int warp = tid >> 5, lane = tid & 31;
    const int wr = warp >> 1, wc = warp & 1;      // 4 x 2 warps
    const int wm = wr * (MT * 16), wn = wc * 64;
    const int m0 = blockIdx.y * BM, n0 = blockIdx.x * 128;
    const int NS = K >> 5;

    const __half* A  = (const __half*)Av;
    const float*  Hc = (const float*)Av;

    float acc[MT][8][4];
#pragma unroll
    for (int mt = 0; mt < MT; mt++)
#pragma unroll
        for (int nt = 0; nt < 8; nt++)
#pragma unroll
            for (int i = 0; i < 4; i++) acc[mt][nt][i] = 0.f;

    uint4 stA[MT], stB[2];

    auto loadA = [&](int s) {
#pragma unroll
        for (int i = 0; i < MT; i++) {
            int lin = tid + i * 256;
            int row = lin >> 2, ch = lin & 3;
            if (CONV) {
                int k0 = s * 32 + ch * 8;
                int seg = k0 / ND;
                int col = k0 - seg * ND;
                int gr = m0 + row;
                int n = gr & 255;
                bool ok = (seg == 1) || (seg == 0 && n > 0) || (seg == 2 && n < 255);
                float4 f0 = make_float4(0.f, 0.f, 0.f, 0.f), f1 = f0;
                if (ok) {
                    const float* p = Hc + (size_t)(gr + seg - 1) * ND + col;
                    f0 = *(const float4*)p;
                    f1 = *(const float4*)(p + 4);
                }
                uint4 u;
                *(__half2*)&u.x = __floats2half2_rn(f0.x, f0.y);
                *(__half2*)&u.y = __floats2half2_rn(f0.z, f0.w);
                *(__half2*)&u.z = __floats2half2_rn(f1.x, f1.y);
                *(__half2*)&u.w = __floats2half2_rn(f1.z, f1.w);
                stA[i] = u;
            } else {
                stA[i] = *(const uint4*)(A + (size_t)(m0 + row) * K + s * 32 + ch * 8);
            }
        }
    };
    auto loadB = [&](int s) {
#pragma unroll
        for (int i = 0; i < 2; i++) {
            int lin = tid + i * 256;
            int row = lin >> 4, c8 = (lin & 15) << 3;
            stB[i] = *(const uint4*)(Bw + (size_t)(s * 32 + row) * N + n0 + c8);
        }
    };

    loadA(0); loadB(0);

    for (int s = 0; s < NS; s++) {
        const int buf = s & 1;
#pragma unroll
        for (int i = 0; i < MT; i++) {
            int lin = tid + i * 256;
            int row = lin >> 2, ch = lin & 3;
            *(uint4*)&As[buf][row * LDA + ch * 8] = stA[i];
        }
#pragma unroll
        for (int i = 0; i < 2; i++) {
            int lin = tid + i * 256;
            int row = lin >> 4, c8 = (lin & 15) << 3;
            *(uint4*)&Bs[buf][row * LDB + c8] = stB[i];
        }
        // issue next-slice global loads before the barrier (overlap)
        if (s + 1 < NS) { loadA(s + 1); loadB(s + 1); }
        __syncthreads();

#pragma unroll
        for (int ks = 0; ks < 2; ks++) {
            unsigned af[MT][4], bf[8][2];
#pragma unroll
            for (int mt = 0; mt < MT; mt++) {
                uint32_t aa = (uint32_t)__cvta_generic_to_shared(
                    &As[buf][(wm + mt * 16 + (lane & 15)) * LDA + ks * 16 + ((lane >> 4) << 3)]);
                ldsm4(af[mt], aa);
            }
#pragma unroll
            for (int np = 0; np < 4; np++) {
                uint32_t ba = (uint32_t)__cvta_generic_to_shared(
                    &Bs[buf][(ks * 16 + (lane & 15)) * LDB + wn + np * 16 + ((lane >> 4) << 3)]);
                ldsm4t(bf[np * 2][0], bf[np * 2][1], bf[np * 2 + 1][0], bf[np * 2 + 1][1], ba);
            }
#pragma unroll
            for (int mt = 0; mt < MT; mt++)
#pragma unroll
                for (int nt = 0; nt < 8; nt++)
                    mma_f16(acc[mt][nt], af[mt], bf[nt]);
        }
    }

    // epilogue
#pragma unroll
    for (int mt = 0; mt < MT; mt++) {
#pragma unroll
        for (int nt = 0; nt < 8; nt++) {
#pragma unroll
            for (int half_i = 0; half_i < 2; half_i++) {
                const int row = m0 + wm + mt * 16 + (lane >> 2) + half_i * 8;
                const int col = n0 + wn + nt * 8 + (lane & 3) * 2;
                float2 r;
                r.x = acc[mt][nt][half_i * 2];
                r.y = acc[mt][nt][half_i * 2 + 1];
                if (bias) { r.x += bias[col]; r.y += bias[col + 1]; }
                if (ACT == 1) { r.x = gelu_exact(r.x); r.y = gelu_exact(r.y); }
                if (ACC) {
                    const float* cp = Cin + (size_t)row * N + col;
                    r.x += cp[0]; r.y += cp[1];
                }
                if (OUTH) {
                    __half2* cp = (__half2*)((__half*)Cv + (size_t)row * N + col);
                    *cp = __floats2half2_rn(r.x, r.y);
                } else {
                    *(float2*)((float*)Cv + (size_t)row * N + col) = r;
                }
            }
        }
    }
}

// ---------------------------------------------------------------------------
// Fused weight prep: converts/transposes ALL weights in one launch.
//  blocks [0, 3840): fp32->half copies (wqkv, ffw1, ffw2, wout)
//  blocks [3840, 4032): transpose proj_in_w -> wAH
//  blocks [4032, 4224): transpose proj_out_w -> wBH
//  blocks [4224, 5952): conv weight reshape -> wtH
// ---------------------------------------------------------------------------
#define WP_N1 (2*ND*NFF/4)      // 294912
#define WP_N4 (2*NINNER*ND/4)   // 98304
#define PRE1 3840
#define PRE2 (PRE1 + 192)
#define PRE3 (PRE2 + 192)
#define PRE4 (PRE3 + 1728)
__global__ __launch_bounds__(256) void prep_all(
    const float* __restrict__ wqkv, const float* __restrict__ ffw1,
    const float* __restrict__ ffw2, const float* __restrict__ wout,
    const float* __restrict__ proj_in_w, const float* __restrict__ proj_out_w,
    const float* __restrict__ local_w,
    __half* __restrict__ o1, __half* __restrict__ o2,
    __half* __restrict__ o3, __half* __restrict__ o4,
    __half* __restrict__ wAH, __half* __restrict__ wBH, __half* __restrict__ wtH)
{
    __shared__ float tt[32][33];
    const int blk = blockIdx.x, t = threadIdx.x;
    if (blk < PRE1) {
        int i = blk * 256 + t;
        const float* src; __half* dst; int j;
        if (i < WP_N1)          { src = wqkv; dst = o1; j = i; }
        else if (i < 2 * WP_N1) { src = ffw1; dst = o2; j = i - WP_N1; }
        else if (i < 3 * WP_N1) { src = ffw2; dst = o3; j = i - 2 * WP_N1; }
        else                    { src = wout; dst = o4; j = i - 3 * WP_N1; }
        st4h(dst + (size_t)j * 4, ((const float4*)src)[j]);
    } else if (blk < PRE3) {
        int R, Cc, bx, by;
        const float* src; __half* dst;
        if (blk < PRE2) { int b = blk - PRE1; R = ND; Cc = NC; bx = b % 16; by = b / 16; src = proj_in_w;  dst = wAH; }
        else            { int b = blk - PRE2; R = NC; Cc = ND; bx = b % 12; by = b / 12; src = proj_out_w; dst = wBH; }
        int tx = t & 31, ty = t >> 5;
        int c = bx * 32 + tx, r = by * 32 + ty;
#pragma unroll
        for (int i = 0; i < 32; i += 8)
            tt[ty + i][tx] = src[(size_t)(r + i) * Cc + c];
        __syncthreads();
        int co = by * 32 + tx, ro = bx * 32 + ty;
#pragma unroll
        for (int i = 0; i < 32; i += 8)
            dst[(size_t)(ro + i) * R + co] = __float2half(tt[tx][ty + i]);
    } else {
        int idx = (blk - PRE3) * 256 + t;
        int krow = idx / ND, dout = idx - krow * ND;
        int k = krow / ND, din = krow - k * ND;
        wtH[idx] = __float2half(local_w[(dout * ND + din) * 3 + k]);
    }
}

// ---------------------------------------------------------------------------
// Pool: x[B,C,L] -> xpT[(b*256+n), c] (half). Coalesced loads, 4-lane shuffle
// reduce, 16 channels per block, packed 32B row-chunk stores.
// grid = 16*32 = 512 blocks.
// ---------------------------------------------------------------------------
__global__ __launch_bounds__(256) void pool_kernel(const float* __restrict__ x,
                                                   __half* __restrict__ xpT)
{
    __shared__ float sums[256 * 17];
    const int b = blockIdx.x >> 5, cg = blockIdx.x & 31;
    const int t = threadIdx.x;

#pragma unroll 1
    for (int cc = 0; cc < 16; cc++) {
        const float4* row = (const float4*)(x + (size_t)(b * NC + cg * 16 + cc) * NL);
        float p[4];
#pragma unroll
        for (int j = 0; j < 4; j++) {
            float4 v = row[t + j * 256];
            p[j] = v.x + v.y + v.z + v.w;
        }
#pragma unroll
        for (int j = 0; j < 4; j++) {
            p[j] += __shfl_xor_sync(0xFFFFFFFFu, p[j], 1);
            p[j] += __shfl_xor_sync(0xFFFFFFFFu, p[j], 2);
        }
        if ((t & 3) == 0) {
            int w0 = t >> 2;
#pragma unroll
            for (int j = 0; j < 4; j++)
                sums[(w0 + j * 64) * 17 + cc] = p[j];
        }
    }
    __syncthreads();

    uint4 u[2];
    __half* hb = (__half*)u;
#pragma unroll
    for (int cc = 0; cc < 16; cc++)
        hb[cc] = __float2half(sums[t * 17 + cc] * (1.f / 16.f));
    __half* dst = xpT + (size_t)(b * NTOK + t) * NC + cg * 16;
    *(uint4*)dst = u[0];
    *((uint4*)dst + 1) = u[1];
}

// ---------------------------------------------------------------------------
// LayerNorm over last dim (384). Warp per row. OUTH: half output.
// ---------------------------------------------------------------------------
template<int OUTH>
__global__ __launch_bounds__(256) void ln_kernel(const float* __restrict__ in,
                                                 const float* __restrict__ g,
                                                 const float* __restrict__ b,
                                                 void* __restrict__ outv)
{
    const int wid = threadIdx.x >> 5, lane = threadIdx.x & 31;
    const int row = blockIdx.x * 8 + wid;
    const float* xr = in + (size_t)row * ND;
    float4 v0 = *(const float4*)(xr + lane * 4);
    float4 v1 = *(const float4*)(xr + 128 + lane * 4);
    float4 v2 = *(const float4*)(xr + 256 + lane * 4);
    float s = v0.x + v0.y + v0.z + v0.w + v1.x + v1.y + v1.z + v1.w
            + v2.x + v2.y + v2.z + v2.w;
    float q = v0.x*v0.x + v0.y*v0.y + v0.z*v0.z + v0.w*v0.w
            + v1.x*v1.x + v1.y*v1.y + v1.z*v1.z + v1.w*v1.w
            + v2.x*v2.x + v2.y*v2.y + v2.z*v2.z + v2.w*v2.w;
#pragma unroll
    for (int o = 16; o; o >>= 1) {
        s += __shfl_xor_sync(0xFFFFFFFFu, s, o);
        q += __shfl_xor_sync(0xFFFFFFFFu, q, o);
    }
    const float mean = s * (1.f / ND);
    const float var  = q * (1.f / ND) - mean * mean;
    const float inv  = rsqrtf(var + 1e-5f);
#pragma unroll
    for (int j = 0; j < 3; j++) {
        int col = j * 128 + lane * 4;
        float4 v = (j == 0) ? v0 : (j == 1) ? v1 : v2;
        float4 gg = *(const float4*)(g + col);
        float4 bb = *(const float4*)(b + col);
        float4 r;
        r.x = (v.x - mean) * inv * gg.x + bb.x;
        r.y = (v.y - mean) * inv * gg.y + bb.y;
        r.z = (v.z - mean) * inv * gg.z + bb.z;
        r.w = (v.w - mean) * inv * gg.w + bb.w;
        if (OUTH) st4h((__half*)outv + (size_t)row * ND + col, r);
        else      *(float4*)((float*)outv + (size_t)row * ND + col) = r;
    }
}

// ---------------------------------------------------------------------------
// Linear attention per (b,h); half in (qkv), half out. Internal fp32.
// ---------------------------------------------------------------------------
__device__ __forceinline__ void r1u(float (&acc)[4][4], float a0, float a1,
                                    float a2, float a3, const float4 b)
{
    acc[0][0] += a0 * b.x; acc[0][1] += a0 * b.y; acc[0][2] += a0 * b.z; acc[0][3] += a0 * b.w;
    acc[1][0] += a1 * b.x; acc[1][1] += a1 * b.y; acc[1][2] += a1 * b.z; acc[1][3] += a1 * b.w;
    acc[2][0] += a2 * b.x; acc[2][1] += a2 * b.y; acc[2][2] += a2 * b.z; acc[2][3] += a2 * b.w;
    acc[3][0] += a3 * b.x; acc[3][1] += a3 * b.y; acc[3][2] += a3 * b.z; acc[3][3] += a3 * b.w;
}

__global__ __launch_bounds__(256) void attn_kernel(const __half* __restrict__ qkv,
                                                   const float* __restrict__ rf,
                                                   __half* __restrict__ o)
{
    __shared__ float rf_s[4096];
    __shared__ float bufA[4096];
    __shared__ float bufB[4096];
    const int tid = threadIdx.x;
    const int bh = blockIdx.x;
    const int b = bh >> 3, h = bh & 7;
    const int tq = tid >> 4, tr = tid & 15;

#pragma unroll
    for (int j = 0; j < 4; j++)
        ((float4*)rf_s)[tid + j * 256] = ((const float4*)rf)[tid + j * 256];

    const __half* base = qkv + (size_t)b * NTOK * NFF + h * NDH;

    float kv[4][4];
#pragma unroll
    for (int i = 0; i < 4; i++)
#pragma unroll
        for (int j = 0; j < 4; j++) kv[i][j] = 0.f;

    for (int n0 = 0; n0 < NTOK; n0 += 64) {
        __syncthreads();
#pragma unroll
        for (int j = 0; j < 4; j++) {
            int lin = tid + j * 256;
            int rowi = lin >> 4, c4 = (lin & 15) << 2;
            const __half* rp = base + (size_t)(n0 + rowi) * NFF;
            float4 kk = ld4h(rp + NINNER + c4);
            kk.x = fmaxf(kk.x, 0.f); kk.y = fmaxf(kk.y, 0.f);
            kk.z = fmaxf(kk.z, 0.f); kk.w = fmaxf(kk.w, 0.f);
            *(float4*)&bufA[rowi * 64 + c4] = kk;
            *(float4*)&bufB[rowi * 64 + c4] = ld4h(rp + 2 * NINNER + c4);
        }
        __syncthreads();
#pragma unroll 8
        for (int nn = 0; nn < 64; nn++) {
            float4 ka = *(const float4*)&bufA[nn * 64 + tq * 4];
            float4 vb = *(const float4*)&bufB[nn * 64 + tr * 4];
            r1u(kv, ka.x, ka.y, ka.z, ka.w, vb);
        }
    }
    __syncthreads();
#pragma unroll
    for (int i = 0; i < 4; i++) {
        float4 v = make_float4(kv[i][0], kv[i][1], kv[i][2], kv[i][3]);
        *(float4*)&bufA[(tq * 4 + i) * 64 + tr * 4] = v;
    }
    __syncthreads();

    float w1[4][4];
#pragma unroll
    for (int i = 0; i < 4; i++)
#pragma unroll
        for (int j = 0; j < 4; j++) w1[i][j] = 0.f;
#pragma unroll 8
    for (int dk = 0; dk < 64; dk++) {
        float4 rm = *(const float4*)&rf_s[dk * 64 + tq * 4];
        float4 kd = *(const float4*)&bufA[dk * 64 + tr * 4];
        r1u(w1, rm.x, rm.y, rm.z, rm.w, kd);
    }
    __syncthreads();
#pragma unroll
    for (int i = 0; i < 4; i++) {
        float4 v = make_float4(w1[i][0], w1[i][1], w1[i][2], w1[i][3]);
        *(float4*)&bufB[(tq * 4 + i) * 64 + tr * 4] = v;
    }
    __syncthreads();

    float w2[4][4];
#pragma unroll
    for (int i = 0; i < 4; i++)
#pragma unroll
        for (int j = 0; j < 4; j++) w2[i][j] = 0.f;
#pragma unroll 8
    for (int m = 0; m < 64; m++) {
        float4 wd = *(const float4*)&bufB[m * 64 + tr * 4];
        float r0 = rf_s[(tq * 4 + 0) * 64 + m];
        float r1 = rf_s[(tq * 4 + 1) * 64 + m];
        float r2 = rf_s[(tq * 4 + 2) * 64 + m];
        float r3 = rf_s[(tq * 4 + 3) * 64 + m];
        r1u(w2, r0, r1, r2, r3, wd);
    }
    __syncthreads();
#pragma unroll
    for (int i = 0; i < 4; i++) {
        float4 v = make_float4(w2[i][0], w2[i][1], w2[i][2], w2[i][3]);
        *(float4*)&bufA[(tq * 4 + i) * 64 + tr * 4] = v;
    }
    __syncthreads();

    for (int n0 = 0; n0 < NTOK; n0 += 64) {
#pragma unroll
        for (int j = 0; j < 4; j++) {
            int lin = tid + j * 256;
            int rowi = lin >> 4, c4 = (lin & 15) << 2;
            const __half* rp = base + (size_t)(n0 + rowi) * NFF;
            float4 qq = ld4h(rp + c4);
            qq.x = fmaxf(qq.x, 0.f) * 0.125f; qq.y = fmaxf(qq.y, 0.f) * 0.125f;
            qq.z = fmaxf(qq.z, 0.f) * 0.125f; qq.w = fmaxf(qq.w, 0.f) * 0.125f;
            *(float4*)&bufB[rowi * 64 + c4] = qq;
        }
        __syncthreads();
        float oc[4][4];
#pragma unroll
        for (int i = 0; i < 4; i++)
#pragma unroll
            for (int j = 0; j < 4; j++) oc[i][j] = 0.f;
#pragma unroll 8
        for (int dq = 0; dq < 64; dq++) {
            float4 wd = *(const float4*)&bufA[dq * 64 + tr * 4];
            float q0 = bufB[(tq * 4 + 0) * 64 + dq];
            float q1 = bufB[(tq * 4 + 1) * 64 + dq];
            float q2 = bufB[(tq * 4 + 2) * 64 + dq];
            float q3 = bufB[(tq * 4 + 3) * 64 + dq];
            r1u(oc, q0, q1, q2, q3, wd);
        }
#pragma unroll
        for (int i = 0; i < 4; i++) {
            st4h(o + (size_t)(b * NTOK + n0 + tq * 4 + i) * NINNER + h * NDH + tr * 4,
                 make_float4(oc[i][0], oc[i][1], oc[i][2], oc[i][3]));
        }
        __syncthreads();
    }
}

// ---------------------------------------------------------------------------
// Final (vectorized): out[b,c,l..l+3] = interp(hp) + x
// ---------------------------------------------------------------------------
__global__ __launch_bounds__(256) void final_kernel(const float* __restrict__ hp,
                                                    const float* __restrict__ x,
                                                    float* __restrict__ out)
{
    size_t i4 = (size_t)blockIdx.x * 256 + threadIdx.x;
    size_t idx = i4 * 4;
    int l = (int)(idx & 4095);
    int c = (int)((idx >> 12) & 511);
    int b = (int)(idx >> 21);
    float4 xv = ((const float4*)x)[i4];
    const float* hprow = hp + (size_t)(b * NTOK) * NC + c;
    float4 o;
#pragma unroll
    for (int j = 0; j < 4; j++) {
        float src = fmaxf((l + j + 0.5f) * 0.0625f - 0.5f, 0.f);
        int i0 = (int)src;
        float w = src - (float)i0;
        int i1 = min(i0 + 1, 255);
        float v0 = hprow[(size_t)i0 * NC];
        float v1 = hprow[(size_t)i1 * NC];
        ((float*)&o)[j] = v0 * (1.f - w) + v1 * w + ((const float*)&xv)[j];
    }
    ((float4*)out)[i4] = o;
}

// ---------------------------------------------------------------------------
// Host orchestration
// ---------------------------------------------------------------------------
extern "C" void kernel_launch(void* const* d_in, const int* in_sizes, int n_in,
                              void* d_out, int out_size)
{
    const float* x          = (const float*)d_in[0];
    const float* proj_in_w  = (const float*)d_in[1];
    const float* proj_in_b  = (const float*)d_in[2];
    const float* norm_in_g  = (const float*)d_in[3];
    const float* norm_in_b  = (const float*)d_in[4];
    const float* ln1_g      = (const float*)d_in[5];
    const float* ln1_b      = (const float*)d_in[6];
    const float* wqkv       = (const float*)d_in[7];
    const float* rf         = (const float*)d_in[8];
    const float* wout       = (const float*)d_in[9];
    const float* bout       = (const float*)d_in[10];
    const float* ln2_g      = (const float*)d_in[11];
    const float* ln2_b      = (const float*)d_in[12];
    const float* ffw1       = (const float*)d_in[13];
    const float* ffb1       = (const float*)d_in[14];
    const float* ffw2       = (const float*)d_in[15];
    const float* ffb2       = (const float*)d_in[16];
    const float* local_w    = (const float*)d_in[17];
    const float* local_b    = (const float*)d_in[18];
    const float* norm_out_g = (const float*)d_in[19];
    const float* norm_out_b = (const float*)d_in[20];
    const float* proj_out_w = (const float*)d_in[21];
    const float* proj_out_b = (const float*)d_in[22];
    float* out = (float*)d_out;

    float *h_, *t3_, *hp_;
    __half *xp_, *t2h_, *yh_;
    __half *wqkvH_, *ffw1H_, *ffw2H_, *woutH_, *wAH_, *wBH_, *wtH_;
    cudaGetSymbolAddress((void**)&h_,     g_h);
    cudaGetSymbolAddress((void**)&t3_,    g_t3);
    cudaGetSymbolAddress((void**)&hp_,    g_hp);
    cudaGetSymbolAddress((void**)&xp_,    g_xp);
    cudaGetSymbolAddress((void**)&t2h_,   g_t2h);
    cudaGetSymbolAddress((void**)&yh_,    g_yh);
    cudaGetSymbolAddress((void**)&wqkvH_, g_wqkvH);
    cudaGetSymbolAddress((void**)&ffw1H_, g_ffw1H);
    cudaGetSymbolAddress((void**)&ffw2H_, g_ffw2H);
    cudaGetSymbolAddress((void**)&woutH_, g_woutH);
    cudaGetSymbolAddress((void**)&wAH_,   g_wAH);
    cudaGetSymbolAddress((void**)&wBH_,   g_wBH);
    cudaGetSymbolAddress((void**)&wtH_,   g_wtH);

    // Fused weight prep
    prep_all<<<PRE4, 256>>>(wqkv, ffw1, ffw2, wout, proj_in_w, proj_out_w, local_w,
                            wqkvH_, ffw1H_, ffw2H_, woutH_, wAH_, wBH_, wtH_);

    // 1. pool -> xp (half)
    pool_kernel<<<NB * 32, 256>>>(x, xp_);
    // 2. h = xp @ wAH + proj_in_b   (M=4096, N=384, K=512) -> fp32
    hgemm<1, 0, false, 0, 0><<<dim3(3, 64), 256>>>(
        xp_, wAH_, proj_in_b, nullptr, h_, NROWS, ND, NC);
    // 3. norm_in (fp32 residual)
    ln_kernel<0><<<NROWS / 8, 256>>>(h_, norm_in_g, norm_in_b, h_);

    for (int i = 0; i < 2; i++) {
        ln_kernel<1><<<NROWS / 8, 256>>>(h_, ln1_g + i * ND, ln1_b + i * ND, t2h_);
        hgemm<2, 0, false, 1, 0><<<dim3(12, 32), 256>>>(
            t2h_, wqkvH_ + (size_t)i * ND * NFF, nullptr, nullptr, yh_, NROWS, NFF, ND);
        attn_kernel<<<NB * NHEADS, 256>>>(yh_, rf + i * NDH * NDH, xp_);
        hgemm<1, 0, true, 0, 0><<<dim3(3, 64), 256>>>(
            xp_, woutH_ + (size_t)i * NINNER * ND, bout + i * ND, h_, h_, NROWS, ND, NINNER);
        ln_kernel<1><<<NROWS / 8, 256>>>(h_, ln2_g + i * ND, ln2_b + i * ND, t2h_);
        hgemm<2, 1, false, 1, 0><<<dim3(12, 32), 256>>>(
            t2h_, ffw1H_ + (size_t)i * ND * NFF, ffb1 + i * NFF, nullptr, yh_, NROWS, NFF, ND);
        hgemm<1, 0, true, 0, 0><<<dim3(3, 64), 256>>>(
            yh_, ffw2H_ + (size_t)i * NFF * ND, ffb2 + i * ND, h_, h_, NROWS, ND, NFF);
    }

    // local conv as one GEMM with fused gather: t3 = h + convA(h) @ wtH + local_b
    hgemm<1, 0, true, 0, 1><<<dim3(3, 64), 256>>>(
        (const void*)h_, wtH_, local_b, h_, t3_, NROWS, ND, 3 * ND);
    // norm_out -> half (feeds proj_out)
    ln_kernel<1><<<NROWS / 8, 256>>>(t3_, norm_out_g, norm_out_b, t2h_);
    // hp = t2h @ wBH + proj_out_b   (M=4096, N=512, K=384) -> fp32
    hgemm<1, 0, false, 0, 0><<<dim3(4, 64), 256>>>(
        t2h_, wBH_, proj_out_b, nullptr, hp_, NROWS, NC, ND);
    // interp + residual with x
    final_kernel<<<(NB * NC * NL) / 1024, 256>>>(hp_, x, out);
}

// round 15
// speedup vs baseline: 1.1236x; 1.0215x over previous
#include <cuda_runtime.h>
#include <cuda_fp16.h>
#include <cstdint>
#include <math.h>

// Problem constants
#define NB   16
#define NC   512
#define NL   4096
#define ND   384
#define NTOK 256
#define NROWS 4096      // NB*NTOK
#define NINNER 512
#define NFF  1536
#define NHEADS 8
#define NDH  64

// ---------------------------------------------------------------------------
// Scratch (device globals; allocation-free)
// ---------------------------------------------------------------------------
__device__ alignas(16) float  g_h  [NROWS*ND];      // residual stream (fp32)
__device__ alignas(16) float  g_t3 [NROWS*ND];      // conv out (fp32)
__device__ alignas(16) float  g_hp [NROWS*NC];      // hp for final (fp32)
__device__ alignas(16) __half g_xp [NROWS*NINNER];  // pool out / attn out (half)
__device__ alignas(16) __half g_t2h[NROWS*ND];      // LN outputs (half)
__device__ alignas(16) __half g_yh [NROWS*NFF];     // qkv / ff1 (half)
// half weights
__device__ alignas(16) __half g_wqkvH[2*ND*NFF];    // [K=384][N=1536]
__device__ alignas(16) __half g_ffw1H[2*ND*NFF];    // [K=384][N=1536]
__device__ alignas(16) __half g_ffw2H[2*NFF*ND];    // [K=1536][N=384]
__device__ alignas(16) __half g_woutH[2*NINNER*ND]; // [K=512][N=384]
__device__ alignas(16) __half g_wAH[NC*ND];         // proj_in^T  [512][384]
__device__ alignas(16) __half g_wBH[ND*NC];         // proj_out^T [384][512]
__device__ alignas(16) __half g_wtH[3*ND*ND];       // conv [K=1152][N=384]

__device__ __forceinline__ float gelu_exact(float v) { return v * normcdff(v); }

__device__ __forceinline__ float4 ld4h(const __half* p) {
    uint2 u = *(const uint2*)p;
    float2 fa = __half22float2(*(__half2*)&u.x);
    float2 fb = __half22float2(*(__half2*)&u.y);
    return make_float4(fa.x, fa.y, fb.x, fb.y);
}
__device__ __forceinline__ void st4h(__half* p, float4 v) {
    uint2 u;
    *(__half2*)&u.x = __floats2half2_rn(v.x, v.y);
    *(__half2*)&u.y = __floats2half2_rn(v.z, v.w);
    *(uint2*)p = u;
}

__device__ __forceinline__ void mma_f16(float (&d)[4], const unsigned (&a)[4],
                                        const unsigned (&b)[2]) {
    asm volatile(
        "mma.sync.aligned.m16n8k16.row.col.f32.f16.f16.f32 "
        "{%0,%1,%2,%3}, {%4,%5,%6,%7}, {%8,%9}, {%0,%1,%2,%3};\n"
        : "+f"(d[0]), "+f"(d[1]), "+f"(d[2]), "+f"(d[3])
        : "r"(a[0]), "r"(a[1]), "r"(a[2]), "r"(a[3]), "r"(b[0]), "r"(b[1]));
}

__device__ __forceinline__ void ldsm4(unsigned (&r)[4], uint32_t addr) {
    asm volatile("ldmatrix.sync.aligned.m8n8.x4.shared.b16 {%0,%1,%2,%3}, [%4];"
                 : "=r"(r[0]), "=r"(r[1]), "=r"(r[2]), "=r"(r[3]) : "r"(addr));
}
__device__ __forceinline__ void ldsm4t(unsigned& r0, unsigned& r1,
                                       unsigned& r2, unsigned& r3, uint32_t addr) {
    asm volatile("ldmatrix.sync.aligned.m8n8.x4.trans.shared.b16 {%0,%1,%2,%3}, [%4];"
                 : "=r"(r0), "=r"(r1), "=r"(r2), "=r"(r3) : "r"(addr));
}

#define CP16(dst, src) \
    asm volatile("cp.async.cg.shared.global [%0], [%1], 16;\n" :: "r"(dst), "l"(src))
#define CPCOMMIT() asm volatile("cp.async.commit_group;\n" ::)
#define CPWAIT1()  asm volatile("cp.async.wait_group 1;\n" ::)

// ---------------------------------------------------------------------------
// fp16 mma.sync GEMM, 3-stage cp.async pipeline. BM=MT*64, BN=128, BK=32.
// 256 threads = 8 warps (4x2); warp tile (MT*16)x64.
// LDA=40 halves (80B rows), LDB=136 (272B): 16B-aligned, conflict-free.
// Stage safety: at iter s, issue(s+2) rewrites stage (s-1)%3 after sync(s),
// which all warps reach only after mma(s-1). wait_group(1) + unconditional
// commits guarantee stage s is resident before compute.
// OUTH=1: half output. ACC adds fp32 Cin. ACT=1: exact GELU.
// ---------------------------------------------------------------------------
template<int MT, int ACT, bool ACC, int OUTH>
__global__ __launch_bounds__(256, 2) void hgemm(
    const __half* __restrict__ A, const __half* __restrict__ Bw,
    const float* __restrict__ bias, const float* __restrict__ Cin,
    void* __restrict__ Cv, int M, int N, int K)
{
    constexpr int BM  = MT * 64;
    constexpr int LDA = 40;
    constexpr int LDB = 136;
    constexpr int ASZ = BM * LDA;
    constexpr int STG = ASZ + 32 * LDB;

    extern __shared__ __half sm[];

    const int tid = threadIdx.x;
    const int warp = tid >> 5, lane = tid & 31;
    const int wr = warp >> 1, wc = warp & 1;      // 4 x 2 warps
    const int wm = wr * (MT * 16), wn = wc * 64;
    const int m0 = blockIdx.y * BM, n0 = blockIdx.x * 128;
    const int NS = K >> 5;

    float acc[MT][8][4];
#pragma unroll
    for (int mt = 0; mt < MT; mt++)
#pragma unroll
        for (int nt = 0; nt < 8; nt++)
#pragma unroll
            for (int i = 0; i < 4; i++) acc[mt][nt][i] = 0.f;

    auto issue = [&](int s) {
        if (s < NS) {
            __half* As = sm + (s % 3) * STG;
            __half* Bs = As + ASZ;
#pragma unroll
            for (int i = 0; i < MT; i++) {
                int lin = tid + i * 256;
                int row = lin >> 2, ch = lin & 3;
                uint32_t d = (uint32_t)__cvta_generic_to_shared(As + row * LDA + ch * 8);
                CP16(d, A + (size_t)(m0 + row) * K + s * 32 + ch * 8);
            }
#pragma unroll
            for (int i = 0; i < 2; i++) {
                int lin = tid + i * 256;
                int row = lin >> 4, c8 = (lin & 15) << 3;
                uint32_t d = (uint32_t)__cvta_generic_to_shared(Bs + row * LDB + c8);
                CP16(d, Bw + (size_t)(s * 32 + row) * N + n0 + c8);
            }
        }
        CPCOMMIT();
    };

    issue(0); issue(1);

    for (int s = 0; s < NS; s++) {
        CPWAIT1();
        __syncthreads();
        issue(s + 2);

        const __half* As = sm + (s % 3) * STG;
        const __half* Bs = As + ASZ;
#pragma unroll
        for (int ks = 0; ks < 2; ks++) {
            unsigned af[MT][4], bf[8][2];
#pragma unroll
            for (int mt = 0; mt < MT; mt++) {
                uint32_t aa = (uint32_t)__cvta_generic_to_shared(
                    As + (wm + mt * 16 + (lane & 15)) * LDA + ks * 16 + ((lane >> 4) << 3));
                ldsm4(af[mt], aa);
            }
#pragma unroll
            for (int np = 0; np < 4; np++) {
                uint32_t ba = (uint32_t)__cvta_generic_to_shared(
                    Bs + (ks * 16 + (lane & 15)) * LDB + wn + np * 16 + ((lane >> 4) << 3));
                ldsm4t(bf[np * 2][0], bf[np * 2][1], bf[np * 2 + 1][0], bf[np * 2 + 1][1], ba);
            }
#pragma unroll
            for (int mt = 0; mt < MT; mt++)
#pragma unroll
                for (int nt = 0; nt < 8; nt++)
                    mma_f16(acc[mt][nt], af[mt], bf[nt]);
        }
    }

    // epilogue
#pragma unroll
    for (int mt = 0; mt < MT; mt++) {
#pragma unroll
        for (int nt = 0; nt < 8; nt++) {
#pragma unroll
            for (int half_i = 0; half_i < 2; half_i++) {
                const int row = m0 + wm + mt * 16 + (lane >> 2) + half_i * 8;
                const int col = n0 + wn + nt * 8 + (lane & 3) * 2;
                float2 r;
                r.x = acc[mt][nt][half_i * 2];
                r.y = acc[mt][nt][half_i * 2 + 1];
                if (bias) { r.x += bias[col]; r.y += bias[col + 1]; }
                if (ACT == 1) { r.x = gelu_exact(r.x); r.y = gelu_exact(r.y); }
                if (ACC) {
                    const float* cp = Cin + (size_t)row * N + col;
                    r.x += cp[0]; r.y += cp[1];
                }
                if (OUTH) {
                    __half2* cp = (__half2*)((__half*)Cv + (size_t)row * N + col);
                    *cp = __floats2half2_rn(r.x, r.y);
                } else {
                    *(float2*)((float*)Cv + (size_t)row * N + col) = r;
                }
            }
        }
    }
}

// ---------------------------------------------------------------------------
// Conv GEMM: BM=64, fused +-1-token gather from fp32 h (register staged,
// 2-stage static smem; proven in R10/R13).
// t3 = h + convA(h) @ wtH + local_b
// ---------------------------------------------------------------------------
__global__ __launch_bounds__(256, 2) void hgemm_conv(
    const float* __restrict__ Hc, const __half* __restrict__ Bw,
    const float* __restrict__ bias, const float* __restrict__ Cin,
    float* __restrict__ C, int M, int N, int K)
{
    constexpr int LDA = 40;
    constexpr int LDB = 136;

    __shared__ alignas(16) __half As[2][64 * LDA];
    __shared__ alignas(16) __half Bs[2][32 * LDB];

    const int tid = threadIdx.x;
    const int warp = tid >> 5, lane = tid & 31;
    const int wr = warp >> 1, wc = warp & 1;
    const int wm = wr * 16, wn = wc * 64;
    const int m0 = blockIdx.y * 64, n0 = blockIdx.x * 128;
    const int NS = K >> 5;

    float acc[8][4];
#pragma unroll
    for (int nt = 0; nt < 8; nt++)
#pragma unroll
        for (int i = 0; i < 4; i++) acc[nt][i] = 0.f;

    uint4 stA, stB[2];
    const int a_row = tid >> 2, a_ch = tid & 3;

    auto loadA = [&](int s) {
        int k0 = s * 32 + a_ch * 8;
        int seg = k0 / ND;
        int col = k0 - seg * ND;
        int gr = m0 + a_row;
        int n = gr & 255;
        bool ok = (seg == 1) || (seg == 0 && n > 0) || (seg == 2 && n < 255);
        float4 f0 = make_float4(0.f, 0.f, 0.f, 0.f), f1 = f0;
        if (ok) {
            const float* p = Hc + (size_t)(gr + seg - 1) * ND + col;
            f0 = *(const float4*)p;
            f1 = *(const float4*)(p + 4);
        }
        uint4 u;
        *(__half2*)&u.x = __floats2half2_rn(f0.x, f0.y);
        *(__half2*)&u.y = __floats2half2_rn(f0.z, f0.w);
        *(__half2*)&u.z = __floats2half2_rn(f1.x, f1.y);
        *(__half2*)&u.w = __floats2half2_rn(f1.z, f1.w);
        stA = u;
    };
    auto loadB = [&](int s) {
#pragma unroll
        for (int i = 0; i < 2; i++) {
            int lin = tid + i * 256;
            int row = lin >> 4, c8 = (lin & 15) << 3;
            stB[i] = *(const uint4*)(Bw + (size_t)(s * 32 + row) * N + n0 + c8);
        }
    };

    loadA(0); loadB(0);

    for (int s = 0; s < NS; s++) {
        const int buf = s & 1;
        *(uint4*)&As[buf][a_row * LDA + a_ch * 8] = stA;
#pragma unroll
        for (int i = 0; i < 2; i++) {
            int lin = tid + i * 256;
            int row = lin >> 4, c8 = (lin & 15) << 3;
            *(uint4*)&Bs[buf][row * LDB + c8] = stB[i];
        }
        if (s + 1 < NS) { loadA(s + 1); loadB(s + 1); }
        __syncthreads();

#pragma unroll
        for (int ks = 0; ks < 2; ks++) {
            unsigned af[4], bf[8][2];
            uint32_t aa = (uint32_t)__cvta_generic_to_shared(
                &As[buf][(wm + (lane & 15)) * LDA + ks * 16 + ((lane >> 4) << 3)]);
            ldsm4(af, aa);
#pragma unroll
            for (int np = 0; np < 4; np++) {
                uint32_t ba = (uint32_t)__cvta_generic_to_shared(
                    &Bs[buf][(ks * 16 + (lane & 15)) * LDB + wn + np * 16 + ((lane >> 4) << 3)]);
                ldsm4t(bf[np * 2][0], bf[np * 2][1], bf[np * 2 + 1][0], bf[np * 2 + 1][1], ba);
            }
#pragma unroll
            for (int nt = 0; nt < 8; nt++)
                mma_f16(acc[nt], af, bf[nt]);
        }
    }

#pragma unroll
    for (int nt = 0; nt < 8; nt++) {
#pragma unroll
        for (int half_i = 0; half_i < 2; half_i++) {
            const int row = m0 + wm + (lane >> 2) + half_i * 8;
            const int col = n0 + wn + nt * 8 + (lane & 3) * 2;
            float2 r;
            r.x = acc[nt][half_i * 2] + bias[col];
            r.y = acc[nt][half_i * 2 + 1] + bias[col + 1];
            const float* cp = Cin + (size_t)row * N + col;
            r.x += cp[0]; r.y += cp[1];
            *(float2*)(C + (size_t)row * N + col) = r;
        }
    }
}

// ---------------------------------------------------------------------------
// Fused weight prep: converts/transposes ALL weights in one launch.
// ---------------------------------------------------------------------------
#define WP_N1 (2*ND*NFF/4)      // 294912
#define WP_N4 (2*NINNER*ND/4)   // 98304
#define PRE1 3840
#define PRE2 (PRE1 + 192)
#define PRE3 (PRE2 + 192)
#define PRE4 (PRE3 + 1728)
__global__ __launch_bounds__(256) void prep_all(
    const float* __restrict__ wqkv, const float* __restrict__ ffw1,
    const float* __restrict__ ffw2, const float* __restrict__ wout,
    const float* __restrict__ proj_in_w, const float* __restrict__ proj_out_w,
    const float* __restrict__ local_w,
    __half* __restrict__ o1, __half* __restrict__ o2,
    __half* __restrict__ o3, __half* __restrict__ o4,
    __half* __restrict__ wAH, __half* __restrict__ wBH, __half* __restrict__ wtH)
{
    __shared__ float tt[32][33];
    const int blk = blockIdx.x, t = threadIdx.x;
    if (blk < PRE1) {
        int i = blk * 256 + t;
        const float* src; __half* dst; int j;
        if (i < WP_N1)          { src = wqkv; dst = o1; j = i; }
        else if (i < 2 * WP_N1) { src = ffw1; dst = o2; j = i - WP_N1; }
        else if (i < 3 * WP_N1) { src = ffw2; dst = o3; j = i - 2 * WP_N1; }
        else                    { src = wout; dst = o4; j = i - 3 * WP_N1; }
        st4h(dst + (size_t)j * 4, ((const float4*)src)[j]);
    } else if (blk < PRE3) {
        int R, Cc, bx, by;
        const float* src; __half* dst;
        if (blk < PRE2) { int b = blk - PRE1; R = ND; Cc = NC; bx = b % 16; by = b / 16; src = proj_in_w;  dst = wAH; }
        else            { int b = blk - PRE2; R = NC; Cc = ND; bx = b % 12; by = b / 12; src = proj_out_w; dst = wBH; }
        int tx = t & 31, ty = t >> 5;
        int c = bx * 32 + tx, r = by * 32 + ty;
#pragma unroll
        for (int i = 0; i < 32; i += 8)
            tt[ty + i][tx] = src[(size_t)(r + i) * Cc + c];
        __syncthreads();
        int co = by * 32 + tx, ro = bx * 32 + ty;
#pragma unroll
        for (int i = 0; i < 32; i += 8)
            dst[(size_t)(ro + i) * R + co] = __float2half(tt[tx][ty + i]);
    } else {
        int idx = (blk - PRE3) * 256 + t;
        int krow = idx / ND, dout = idx - krow * ND;
        int k = krow / ND, din = krow - k * ND;
        wtH[idx] = __float2half(local_w[(dout * ND + din) * 3 + k]);
    }
}

// ---------------------------------------------------------------------------
// Pool: x[B,C,L] -> xpT[(b*256+n), c] (half). Coalesced loads, 4-lane shuffle
// reduce, 16 channels per block, packed 32B row-chunk stores.
// ---------------------------------------------------------------------------
__global__ __launch_bounds__(256) void pool_kernel(const float* __restrict__ x,
                                                   __half* __restrict__ xpT)
{
    __shared__ float sums[256 * 17];
    const int b = blockIdx.x >> 5, cg = blockIdx.x & 31;
    const int t = threadIdx.x;

#pragma unroll 1
    for (int cc = 0; cc < 16; cc++) {
        const float4* row = (const float4*)(x + (size_t)(b * NC + cg * 16 + cc) * NL);
        float p[4];
#pragma unroll
        for (int j = 0; j < 4; j++) {
            float4 v = row[t + j * 256];
            p[j] = v.x + v.y + v.z + v.w;
        }
#pragma unroll
        for (int j = 0; j < 4; j++) {
            p[j] += __shfl_xor_sync(0xFFFFFFFFu, p[j], 1);
            p[j] += __shfl_xor_sync(0xFFFFFFFFu, p[j], 2);
        }
        if ((t & 3) == 0) {
            int w0 = t >> 2;
#pragma unroll
            for (int j = 0; j < 4; j++)
                sums[(w0 + j * 64) * 17 + cc] = p[j];
        }
    }
    __syncthreads();

    uint4 u[2];
    __half* hb = (__half*)u;
#pragma unroll
    for (int cc = 0; cc < 16; cc++)
        hb[cc] = __float2half(sums[t * 17 + cc] * (1.f / 16.f));
    __half* dst = xpT + (size_t)(b * NTOK + t) * NC + cg * 16;
    *(uint4*)dst = u[0];
    *((uint4*)dst + 1) = u[1];
}

// ---------------------------------------------------------------------------
// LayerNorm over last dim (384). Warp per row. OUTH: half output.
// ---------------------------------------------------------------------------
template<int OUTH>
__global__ __launch_bounds__(256) void ln_kernel(const float* __restrict__ in,
                                                 const float* __restrict__ g,
                                                 const float* __restrict__ b,
                                                 void* __restrict__ outv)
{
    const int wid = threadIdx.x >> 5, lane = threadIdx.x & 31;
    const int row = blockIdx.x * 8 + wid;
    const float* xr = in + (size_t)row * ND;
    float4 v0 = *(const float4*)(xr + lane * 4);
    float4 v1 = *(const float4*)(xr + 128 + lane * 4);
    float4 v2 = *(const float4*)(xr + 256 + lane * 4);
    float s = v0.x + v0.y + v0.z + v0.w + v1.x + v1.y + v1.z + v1.w
            + v2.x + v2.y + v2.z + v2.w;
    float q = v0.x*v0.x + v0.y*v0.y + v0.z*v0.z + v0.w*v0.w
            + v1.x*v1.x + v1.y*v1.y + v1.z*v1.z + v1.w*v1.w
            + v2.x*v2.x + v2.y*v2.y + v2.z*v2.z + v2.w*v2.w;
#pragma unroll
    for (int o = 16; o; o >>= 1) {
        s += __shfl_xor_sync(0xFFFFFFFFu, s, o);
        q += __shfl_xor_sync(0xFFFFFFFFu, q, o);
    }
    const float mean = s * (1.f / ND);
    const float var  = q * (1.f / ND) - mean * mean;
    const float inv  = rsqrtf(var + 1e-5f);
#pragma unroll
    for (int j = 0; j < 3; j++) {
        int col = j * 128 + lane * 4;
        float4 v = (j == 0) ? v0 : (j == 1) ? v1 : v2;
        float4 gg = *(const float4*)(g + col);
        float4 bb = *(const float4*)(b + col);
        float4 r;
        r.x = (v.x - mean) * inv * gg.x + bb.x;
        r.y = (v.y - mean) * inv * gg.y + bb.y;
        r.z = (v.z - mean) * inv * gg.z + bb.z;
        r.w = (v.w - mean) * inv * gg.w + bb.w;
        if (OUTH) st4h((__half*)outv + (size_t)row * ND + col, r);
        else      *(float4*)((float*)outv + (size_t)row * ND + col) = r;
    }
}

// ---------------------------------------------------------------------------
// Linear attention per (b,h); half in (qkv), half out. Internal fp32.
// ---------------------------------------------------------------------------
__device__ __forceinline__ void r1u(float (&acc)[4][4], float a0, float a1,
                                    float a2, float a3, const float4 b)
{
    acc[0][0] += a0 * b.x; acc[0][1] += a0 * b.y; acc[0][2] += a0 * b.z; acc[0][3] += a0 * b.w;
    acc[1][0] += a1 * b.x; acc[1][1] += a1 * b.y; acc[1][2] += a1 * b.z; acc[1][3] += a1 * b.w;
    acc[2][0] += a2 * b.x; acc[2][1] += a2 * b.y; acc[2][2] += a2 * b.z; acc[2][3] += a2 * b.w;
    acc[3][0] += a3 * b.x; acc[3][1] += a3 * b.y; acc[3][2] += a3 * b.z; acc[3][3] += a3 * b.w;
}

__global__ __launch_bounds__(256) void attn_kernel(const __half* __restrict__ qkv,
                                                   const float* __restrict__ rf,
                                                   __half* __restrict__ o)
{
    __shared__ float rf_s[4096];
    __shared__ float bufA[4096];
    __shared__ float bufB[4096];
    const int tid = threadIdx.x;
    const int bh = blockIdx.x;
    const int b = bh >> 3, h = bh & 7;
    const int tq = tid >> 4, tr = tid & 15;

#pragma unroll
    for (int j = 0; j < 4; j++)
        ((float4*)rf_s)[tid + j * 256] = ((const float4*)rf)[tid + j * 256];

    const __half* base = qkv + (size_t)b * NTOK * NFF + h * NDH;

    float kv[4][4];
#pragma unroll
    for (int i = 0; i < 4; i++)
#pragma unroll
        for (int j = 0; j < 4; j++) kv[i][j] = 0.f;

    for (int n0 = 0; n0 < NTOK; n0 += 64) {
        __syncthreads();
#pragma unroll
        for (int j = 0; j < 4; j++) {
            int lin = tid + j * 256;
            int rowi = lin >> 4, c4 = (lin & 15) << 2;
            const __half* rp = base + (size_t)(n0 + rowi) * NFF;
            float4 kk = ld4h(rp + NINNER + c4);
            kk.x = fmaxf(kk.x, 0.f); kk.y = fmaxf(kk.y, 0.f);
            kk.z = fmaxf(kk.z, 0.f); kk.w = fmaxf(kk.w, 0.f);
            *(float4*)&bufA[rowi * 64 + c4] = kk;
            *(float4*)&bufB[rowi * 64 + c4] = ld4h(rp + 2 * NINNER + c4);
        }
        __syncthreads();
#pragma unroll 8
        for (int nn = 0; nn < 64; nn++) {
            float4 ka = *(const float4*)&bufA[nn * 64 + tq * 4];
            float4 vb = *(const float4*)&bufB[nn * 64 + tr * 4];
            r1u(kv, ka.x, ka.y, ka.z, ka.w, vb);
        }
    }
    __syncthreads();
#pragma unroll
    for (int i = 0; i < 4; i++) {
        float4 v = make_float4(kv[i][0], kv[i][1], kv[i][2], kv[i][3]);
        *(float4*)&bufA[(tq * 4 + i) * 64 + tr * 4] = v;
    }
    __syncthreads();

    float w1[4][4];
#pragma unroll
    for (int i = 0; i < 4; i++)
#pragma unroll
        for (int j = 0; j < 4; j++) w1[i][j] = 0.f;
#pragma unroll 8
    for (int dk = 0; dk < 64; dk++) {
        float4 rm = *(const float4*)&rf_s[dk * 64 + tq * 4];
        float4 kd = *(const float4*)&bufA[dk * 64 + tr * 4];
        r1u(w1, rm.x, rm.y, rm.z, rm.w, kd);
    }
    __syncthreads();
#pragma unroll
    for (int i = 0; i < 4; i++) {
        float4 v = make_float4(w1[i][0], w1[i][1], w1[i][2], w1[i][3]);
        *(float4*)&bufB[(tq * 4 + i) * 64 + tr * 4] = v;
    }
    __syncthreads();

    float w2[4][4];
#pragma unroll
    for (int i = 0; i < 4; i++)
#pragma unroll
        for (int j = 0; j < 4; j++) w2[i][j] = 0.f;
#pragma unroll 8
    for (int m = 0; m < 64; m++) {
        float4 wd = *(const float4*)&bufB[m * 64 + tr * 4];
        float r0 = rf_s[(tq * 4 + 0) * 64 + m];
        float r1 = rf_s[(tq * 4 + 1) * 64 + m];
        float r2 = rf_s[(tq * 4 + 2) * 64 + m];
        float r3 = rf_s[(tq * 4 + 3) * 64 + m];
        r1u(w2, r0, r1, r2, r3, wd);
    }
    __syncthreads();
#pragma unroll
    for (int i = 0; i < 4; i++) {
        float4 v = make_float4(w2[i][0], w2[i][1], w2[i][2], w2[i][3]);
        *(float4*)&bufA[(tq * 4 + i) * 64 + tr * 4] = v;
    }
    __syncthreads();

    for (int n0 = 0; n0 < NTOK; n0 += 64) {
#pragma unroll
        for (int j = 0; j < 4; j++) {
            int lin = tid + j * 256;
            int rowi = lin >> 4, c4 = (lin & 15) << 2;
            const __half* rp = base + (size_t)(n0 + rowi) * NFF;
            float4 qq = ld4h(rp + c4);
            qq.x = fmaxf(qq.x, 0.f) * 0.125f; qq.y = fmaxf(qq.y, 0.f) * 0.125f;
            qq.z = fmaxf(qq.z, 0.f) * 0.125f; qq.w = fmaxf(qq.w, 0.f) * 0.125f;
            *(float4*)&bufB[rowi * 64 + c4] = qq;
        }
        __syncthreads();
        float oc[4][4];
#pragma unroll
        for (int i = 0; i < 4; i++)
#pragma unroll
            for (int j = 0; j < 4; j++) oc[i][j] = 0.f;
#pragma unroll 8
        for (int dq = 0; dq < 64; dq++) {
            float4 wd = *(const float4*)&bufA[dq * 64 + tr * 4];
            float q0 = bufB[(tq * 4 + 0) * 64 + dq];
            float q1 = bufB[(tq * 4 + 1) * 64 + dq];
            float q2 = bufB[(tq * 4 + 2) * 64 + dq];
            float q3 = bufB[(tq * 4 + 3) * 64 + dq];
            r1u(oc, q0, q1, q2, q3, wd);
        }
#pragma unroll
        for (int i = 0; i < 4; i++) {
            st4h(o + (size_t)(b * NTOK + n0 + tq * 4 + i) * NINNER + h * NDH + tr * 4,
                 make_float4(oc[i][0], oc[i][1], oc[i][2], oc[i][3]));
        }
        __syncthreads();
    }
}

// ---------------------------------------------------------------------------
// Final (vectorized): out[b,c,l..l+3] = interp(hp) + x
// ---------------------------------------------------------------------------
__global__ __launch_bounds__(256) void final_kernel(const float* __restrict__ hp,
                                                    const float* __restrict__ x,
                                                    float* __restrict__ out)
{
    size_t i4 = (size_t)blockIdx.x * 256 + threadIdx.x;
    size_t idx = i4 * 4;
    int l = (int)(idx & 4095);
    int c = (int)((idx >> 12) & 511);
    int b = (int)(idx >> 21);
    float4 xv = ((const float4*)x)[i4];
    const float* hprow = hp + (size_t)(b * NTOK) * NC + c;
    float4 o;
#pragma unroll
    for (int j = 0; j < 4; j++) {
        float src = fmaxf((l + j + 0.5f) * 0.0625f - 0.5f, 0.f);
        int i0 = (int)src;
        float w = src - (float)i0;
        int i1 = min(i0 + 1, 255);
        float v0 = hprow[(size_t)i0 * NC];
        float v1 = hprow[(size_t)i1 * NC];
        ((float*)&o)[j] = v0 * (1.f - w) + v1 * w + ((const float*)&xv)[j];
    }
    ((float4*)out)[i4] = o;
}

// ---------------------------------------------------------------------------
// Host orchestration
// ---------------------------------------------------------------------------
extern "C" void kernel_launch(void* const* d_in, const int* in_sizes, int n_in,
                              void* d_out, int out_size)
{
    const float* x          = (const float*)d_in[0];
    const float* proj_in_w  = (const float*)d_in[1];
    const float* proj_in_b  = (const float*)d_in[2];
    const float* norm_in_g  = (const float*)d_in[3];
    const float* norm_in_b  = (const float*)d_in[4];
    const float* ln1_g      = (const float*)d_in[5];
    const float* ln1_b      = (const float*)d_in[6];
    const float* wqkv       = (const float*)d_in[7];
    const float* rf         = (const float*)d_in[8];
    const float* wout       = (const float*)d_in[9];
    const float* bout       = (const float*)d_in[10];
    const float* ln2_g      = (const float*)d_in[11];
    const float* ln2_b      = (const float*)d_in[12];
    const float* ffw1       = (const float*)d_in[13];
    const float* ffb1       = (const float*)d_in[14];
    const float* ffw2       = (const float*)d_in[15];
    const float* ffb2       = (const float*)d_in[16];
    const float* local_w    = (const float*)d_in[17];
    const float* local_b    = (const float*)d_in[18];
    const float* norm_out_g = (const float*)d_in[19];
    const float* norm_out_b = (const float*)d_in[20];
    const float* proj_out_w = (const float*)d_in[21];
    const float* proj_out_b = (const float*)d_in[22];
    float* out = (float*)d_out;

    float *h_, *t3_, *hp_;
    __half *xp_, *t2h_, *yh_;
    __half *wqkvH_, *ffw1H_, *ffw2H_, *woutH_, *wAH_, *wBH_, *wtH_;
    cudaGetSymbolAddress((void**)&h_,     g_h);
    cudaGetSymbolAddress((void**)&t3_,    g_t3);
    cudaGetSymbolAddress((void**)&hp_,    g_hp);
    cudaGetSymbolAddress((void**)&xp_,    g_xp);
    cudaGetSymbolAddress((void**)&t2h_,   g_t2h);
    cudaGetSymbolAddress((void**)&yh_,    g_yh);
    cudaGetSymbolAddress((void**)&wqkvH_, g_wqkvH);
    cudaGetSymbolAddress((void**)&ffw1H_, g_ffw1H);
    cudaGetSymbolAddress((void**)&ffw2H_, g_ffw2H);
    cudaGetSymbolAddress((void**)&woutH_, g_woutH);
    cudaGetSymbolAddress((void**)&wAH_,   g_wAH);
    cudaGetSymbolAddress((void**)&wBH_,   g_wBH);
    cudaGetSymbolAddress((void**)&wtH_,   g_wtH);

    // dynamic smem: MT=1 -> 41472 B (below default limit), MT=2 -> 56832 B
    const int smem1 = 3 * (64 * 40 + 32 * 136) * 2;
    const int smem2 = 3 * (128 * 40 + 32 * 136) * 2;
    cudaFuncSetAttribute(hgemm<2, 0, false, 1>,
        cudaFuncAttributeMaxDynamicSharedMemorySize, smem2);
    cudaFuncSetAttribute(hgemm<2, 1, false, 1>,
        cudaFuncAttributeMaxDynamicSharedMemorySize, smem2);

    // Fused weight prep
    prep_all<<<PRE4, 256>>>(wqkv, ffw1, ffw2, wout, proj_in_w, proj_out_w, local_w,
                            wqkvH_, ffw1H_, ffw2H_, woutH_, wAH_, wBH_, wtH_);

    // 1. pool -> xp (half)
    pool_kernel<<<NB * 32, 256>>>(x, xp_);
    // 2. h = xp @ wAH + proj_in_b   (M=4096, N=384, K=512) -> fp32
    hgemm<1, 0, false, 0><<<dim3(3, 64), 256, smem1>>>(
        xp_, wAH_, proj_in_b, nullptr, h_, NROWS, ND, NC);
    // 3. norm_in (fp32 residual)
    ln_kernel<0><<<NROWS / 8, 256>>>(h_, norm_in_g, norm_in_b, h_);

    for (int i = 0; i < 2; i++) {
        ln_kernel<1><<<NROWS / 8, 256>>>(h_, ln1_g + i * ND, ln1_b + i * ND, t2h_);
        hgemm<2, 0, false, 1><<<dim3(12, 32), 256, smem2>>>(
            t2h_, wqkvH_ + (size_t)i * ND * NFF, nullptr, nullptr, yh_, NROWS, NFF, ND);
        attn_kernel<<<NB * NHEADS, 256>>>(yh_, rf + i * NDH * NDH, xp_);
        hgemm<1, 0, true, 0><<<dim3(3, 64), 256, smem1>>>(
            xp_, woutH_ + (size_t)i * NINNER * ND, bout + i * ND, h_, h_, NROWS, ND, NINNER);
        ln_kernel<1><<<NROWS / 8, 256>>>(h_, ln2_g + i * ND, ln2_b + i * ND, t2h_);
        hgemm<2, 1, false, 1><<<dim3(12, 32), 256, smem2>>>(
            t2h_, ffw1H_ + (size_t)i * ND * NFF, ffb1 + i * NFF, nullptr, yh_, NROWS, NFF, ND);
        hgemm<1, 0, true, 0><<<dim3(3, 64), 256, smem1>>>(
            yh_, ffw2H_ + (size_t)i * NFF * ND, ffb2 + i * ND, h_, h_, NROWS, ND, NFF);
    }

    // local conv GEMM with fused gather: t3 = h + convA(h) @ wtH + local_b
    hgemm_conv<<<dim3(3, 64), 256>>>(h_, wtH_, local_b, h_, t3_, NROWS, ND, 3 * ND);
    // norm_out -> half (feeds proj_out)
    ln_kernel<1><<<NROWS / 8, 256>>>(t3_, norm_out_g, norm_out_b, t2h_);
    // hp = t2h @ wBH + proj_out_b   (M=4096, N=512, K=384) -> fp32
    hgemm<1, 0, false, 0><<<dim3(4, 64), 256, smem1>>>(
        t2h_, wBH_, proj_out_b, nullptr, hp_, NROWS, NC, ND);
    // interp + residual with x
    final_kernel<<<(NB * NC * NL) / 1024, 256>>>(hp_, x, out);
}